// round 1
// baseline (speedup 1.0000x reference)
#include <cuda_runtime.h>
#include <math.h>

// ---------------- problem constants ----------------
#define BQ 2
#define TQ 1024
#define DQ 768
#define LQ 4
#define HQ 12
#define VQ 50257
#define BT (BQ*TQ)            // 2048 rows
#define HD 64                 // head dim

// ---------------- scratch (allocation-free: device globals) ----------------
__device__ float g_x   [BT*DQ];        // residual stream
__device__ float g_h   [BT*DQ];        // layernorm output
__device__ float g_qkv [BT*3*DQ];      // qkv projections
__device__ float g_attn[BT*DQ];        // attention output
__device__ float g_ffn [BT*4*DQ];      // MLP hidden
__device__ float g_nll [BT];           // per-token nll
__device__ float g_logits_fb[102926336]; // fallback logits (BT*VQ) if out has no logits

// ---------------- embedding: x = tok_emb[ids] + pos_emb ----------------
__global__ void embed_kernel(const int* __restrict__ ids,
                             const float* __restrict__ tok,
                             const float* __restrict__ pos,
                             float* __restrict__ x) {
    int i = blockIdx.x * 256 + threadIdx.x;
    if (i >= BT * DQ) return;
    int r = i / DQ, d = i - r * DQ;
    int id = ids[r];
    x[i] = tok[(size_t)id * DQ + d] + pos[(r % TQ) * DQ + d];
}

// ---------------- layernorm (block per row, D=768) ----------------
__global__ void ln_kernel(const float* __restrict__ x,
                          const float* __restrict__ w,
                          const float* __restrict__ b,
                          float* __restrict__ y) {
    int row = blockIdx.x;
    const float* xr = x + (size_t)row * DQ;
    float s = 0.f, q = 0.f;
    for (int i = threadIdx.x; i < DQ; i += 256) { float v = xr[i]; s += v; q += v * v; }
    __shared__ float ss[256], sq[256];
    ss[threadIdx.x] = s; sq[threadIdx.x] = q; __syncthreads();
    for (int o = 128; o > 0; o >>= 1) {
        if (threadIdx.x < o) { ss[threadIdx.x] += ss[threadIdx.x + o]; sq[threadIdx.x] += sq[threadIdx.x + o]; }
        __syncthreads();
    }
    float mean = ss[0] * (1.f / DQ);
    float var  = sq[0] * (1.f / DQ) - mean * mean;
    float inv  = rsqrtf(var + 1e-5f);
    float* yr = y + (size_t)row * DQ;
    for (int i = threadIdx.x; i < DQ; i += 256)
        yr[i] = (xr[i] - mean) * inv * w[i] + b[i];
}

// ---------------- generic SGEMM: C = A[M,K] * B (+bias, +res, +gelu) ----------------
// TRANSB=false: B is [K,N] row-major.  TRANSB=true: B is [N,K] row-major (C = A * B^T).
// EPI: 0 = +bias, 1 = +bias +residual, 2 = +bias, GELU(exact)
template<bool TRANSB, int EPI>
__global__ __launch_bounds__(256)
void gemm_kernel(const float* __restrict__ A, const float* __restrict__ B,
                 const float* __restrict__ bias, const float* __restrict__ res,
                 float* __restrict__ C, int M, int N, int K) {
    __shared__ float As[16][64];
    __shared__ float Bs[16][64];
    const int tid = threadIdx.x;
    const int m0 = blockIdx.y * 64;
    const int n0 = blockIdx.x * 64;
    const int tx = tid & 15, ty = tid >> 4;
    float acc[4][4] = {};

    for (int k0 = 0; k0 < K; k0 += 16) {
        // load A tile (64 rows x 16 k)
        #pragma unroll
        for (int i = tid; i < 64 * 16; i += 256) {
            int r = i >> 4, c = i & 15;
            int gm = m0 + r;
            As[c][r] = (gm < M) ? A[(size_t)gm * K + (k0 + c)] : 0.f;
        }
        // load B tile
        if (!TRANSB) {
            #pragma unroll
            for (int i = tid; i < 16 * 64; i += 256) {
                int r = i >> 6, c = i & 63;
                int gn = n0 + c;
                Bs[r][c] = (gn < N) ? B[(size_t)(k0 + r) * N + gn] : 0.f;
            }
        } else {
            #pragma unroll
            for (int i = tid; i < 64 * 16; i += 256) {
                int n = i >> 4, c = i & 15;
                int gn = n0 + n;
                Bs[c][n] = (gn < N) ? B[(size_t)gn * K + (k0 + c)] : 0.f;
            }
        }
        __syncthreads();
        #pragma unroll
        for (int kk = 0; kk < 16; kk++) {
            float a[4], bv[4];
            #pragma unroll
            for (int i = 0; i < 4; i++) a[i]  = As[kk][ty * 4 + i];
            #pragma unroll
            for (int j = 0; j < 4; j++) bv[j] = Bs[kk][tx * 4 + j];
            #pragma unroll
            for (int i = 0; i < 4; i++)
                #pragma unroll
                for (int j = 0; j < 4; j++)
                    acc[i][j] = fmaf(a[i], bv[j], acc[i][j]);
        }
        __syncthreads();
    }

    #pragma unroll
    for (int i = 0; i < 4; i++) {
        int m = m0 + ty * 4 + i;
        if (m >= M) continue;
        #pragma unroll
        for (int j = 0; j < 4; j++) {
            int n = n0 + tx * 4 + j;
            if (n >= N) continue;
            float v = acc[i][j] + (bias ? bias[n] : 0.f);
            if (EPI == 1) v += res[(size_t)m * N + n];
            if (EPI == 2) v = 0.5f * v * (1.f + erff(v * 0.70710678118654752440f));
            C[(size_t)m * N + n] = v;
        }
    }
}

// ---------------- causal attention: one warp per (b,h,q) row ----------------
// qkv layout: [BT, 3*D]; q at col h*64, k at 768+h*64, v at 1536+h*64
__global__ void attn_kernel(const float* __restrict__ qkv, float* __restrict__ out) {
    const int qi   = blockIdx.x;
    const int h    = blockIdx.y;
    const int b    = blockIdx.z;
    const int lane = threadIdx.x;

    size_t qbase = (size_t)(b * TQ + qi) * (3 * DQ) + h * HD;
    float2 q2 = *(const float2*)(qkv + qbase + 2 * lane);
    q2.x *= 0.125f; q2.y *= 0.125f;   // 1/sqrt(64)

    float m = -1e30f, l = 0.f;
    float2 acc = make_float2(0.f, 0.f);

    for (int k = 0; k <= qi; k++) {
        size_t kb = (size_t)(b * TQ + k) * (3 * DQ) + DQ + h * HD;
        float2 k2 = *(const float2*)(qkv + kb + 2 * lane);
        float s = q2.x * k2.x + q2.y * k2.y;
        #pragma unroll
        for (int o = 16; o > 0; o >>= 1) s += __shfl_xor_sync(0xffffffffu, s, o);
        float mn   = fmaxf(m, s);
        float corr = expf(m - mn);
        float p    = expf(s - mn);
        l = l * corr + p;
        float2 v2 = *(const float2*)(qkv + kb + DQ + 2 * lane);
        acc.x = acc.x * corr + p * v2.x;
        acc.y = acc.y * corr + p * v2.y;
        m = mn;
    }
    float invl = 1.f / l;
    float* o = out + (size_t)(b * TQ + qi) * DQ + h * HD + 2 * lane;
    o[0] = acc.x * invl;
    o[1] = acc.y * invl;
}

// ---------------- per-row NLL via online logsumexp over V ----------------
__global__ void nll_kernel(const float* __restrict__ logits, const int* __restrict__ tgt,
                           float* __restrict__ nll) {
    int row = blockIdx.x;
    const float* lr = logits + (size_t)row * VQ;
    float m = -1e30f, s = 0.f;
    for (int j = threadIdx.x; j < VQ; j += 256) {
        float v = lr[j];
        if (v > m) { s = s * expf(m - v) + 1.f; m = v; }
        else       { s += expf(v - m); }
    }
    __shared__ float sm[256], ssum[256];
    sm[threadIdx.x] = m; ssum[threadIdx.x] = s; __syncthreads();
    for (int o = 128; o > 0; o >>= 1) {
        if (threadIdx.x < o) {
            float m2 = sm[threadIdx.x + o], s2 = ssum[threadIdx.x + o];
            float M  = fmaxf(sm[threadIdx.x], m2);
            ssum[threadIdx.x] = ssum[threadIdx.x] * expf(sm[threadIdx.x] - M) + s2 * expf(m2 - M);
            sm[threadIdx.x]   = M;
        }
        __syncthreads();
    }
    if (threadIdx.x == 0) {
        float lse = sm[0] + logf(ssum[0]);
        int t = tgt[row];
        nll[row] = lse - lr[t];
    }
}

__global__ void loss_kernel(const float* __restrict__ nll, float* __restrict__ loss) {
    __shared__ float s[1024];
    float v = nll[threadIdx.x] + nll[threadIdx.x + 1024];
    s[threadIdx.x] = v; __syncthreads();
    for (int o = 512; o > 0; o >>= 1) {
        if (threadIdx.x < o) s[threadIdx.x] += s[threadIdx.x + o];
        __syncthreads();
    }
    if (threadIdx.x == 0) *loss = s[0] * (1.f / 2048.f);
}

// ---------------- launch ----------------
extern "C" void kernel_launch(void* const* d_in, const int* in_sizes, int n_in,
                              void* d_out, int out_size) {
    const int*   ids  = (const int*)d_in[0];
    const int*   tgt  = (const int*)d_in[1];
    const float* tok  = (const float*)d_in[2];
    const float* pos  = (const float*)d_in[3];
    const float* ln1w = (const float*)d_in[4];
    const float* ln1b = (const float*)d_in[5];
    const float* qkvw = (const float*)d_in[6];
    const float* qkvb = (const float*)d_in[7];
    const float* apw  = (const float*)d_in[8];
    const float* apb  = (const float*)d_in[9];
    const float* ln2w = (const float*)d_in[10];
    const float* ln2b = (const float*)d_in[11];
    const float* fcw  = (const float*)d_in[12];
    const float* fcb  = (const float*)d_in[13];
    const float* pw   = (const float*)d_in[14];
    const float* pb   = (const float*)d_in[15];
    const float* lnfw = (const float*)d_in[16];
    const float* lnfb = (const float*)d_in[17];

    float *x, *h, *qkv, *attn, *ffn, *nll, *lfb;
    cudaGetSymbolAddress((void**)&x,    g_x);
    cudaGetSymbolAddress((void**)&h,    g_h);
    cudaGetSymbolAddress((void**)&qkv,  g_qkv);
    cudaGetSymbolAddress((void**)&attn, g_attn);
    cudaGetSymbolAddress((void**)&ffn,  g_ffn);
    cudaGetSymbolAddress((void**)&nll,  g_nll);
    cudaGetSymbolAddress((void**)&lfb,  g_logits_fb);

    const long long LOGN = (long long)BT * VQ;  // 102,926,336
    float* out    = (float*)d_out;
    float* logits;
    float* lossp  = nullptr;
    if ((long long)out_size > LOGN) {           // [loss, logits...]
        lossp  = out;
        logits = out + ((long long)out_size - LOGN);
    } else if ((long long)out_size == LOGN) {   // logits only
        logits = out;
    } else {                                    // loss only
        lossp  = out;
        logits = lfb;
    }

    embed_kernel<<<(BT * DQ + 255) / 256, 256>>>(ids, tok, pos, x);

    for (int l = 0; l < LQ; l++) {
        ln_kernel<<<BT, 256>>>(x, ln1w + l * DQ, ln1b + l * DQ, h);
        gemm_kernel<false, 0><<<dim3((3 * DQ) / 64, BT / 64), 256>>>(
            h, qkvw + (size_t)l * DQ * 3 * DQ, qkvb + l * 3 * DQ, nullptr, qkv, BT, 3 * DQ, DQ);
        attn_kernel<<<dim3(TQ, HQ, BQ), 32>>>(qkv, attn);
        gemm_kernel<false, 1><<<dim3(DQ / 64, BT / 64), 256>>>(
            attn, apw + (size_t)l * DQ * DQ, apb + l * DQ, x, x, BT, DQ, DQ);
        ln_kernel<<<BT, 256>>>(x, ln2w + l * DQ, ln2b + l * DQ, h);
        gemm_kernel<false, 2><<<dim3((4 * DQ) / 64, BT / 64), 256>>>(
            h, fcw + (size_t)l * DQ * 4 * DQ, fcb + l * 4 * DQ, nullptr, ffn, BT, 4 * DQ, DQ);
        gemm_kernel<false, 1><<<dim3(DQ / 64, BT / 64), 256>>>(
            ffn, pw + (size_t)l * 4 * DQ * DQ, pb + l * DQ, x, x, BT, DQ, 4 * DQ);
    }

    ln_kernel<<<BT, 256>>>(x, lnfw, lnfb, h);
    gemm_kernel<true, 0><<<dim3((VQ + 63) / 64, BT / 64), 256>>>(
        h, tok, nullptr, nullptr, logits, BT, VQ, DQ);

    if (lossp) {
        nll_kernel<<<BT, 256>>>(logits, tgt, nll);
        loss_kernel<<<1, 1024>>>(nll, lossp);
    }
}

// round 2
// speedup vs baseline: 3.7924x; 3.7924x over previous
#include <cuda_runtime.h>
#include <math.h>
#include <stdint.h>

// ---------------- problem constants ----------------
#define BQ 2
#define TQ 1024
#define DQ 768
#define LQ 4
#define HQ 12
#define VQ 50257
#define BT (BQ*TQ)            // 2048 rows
#define HD 64                 // head dim

// ---------------- scratch (allocation-free: device globals) ----------------
__device__ float g_x   [BT*DQ];
__device__ float g_h   [BT*DQ];
__device__ float g_qkv [BT*3*DQ];
__device__ float g_attn[BT*DQ];
__device__ float g_ffn [BT*4*DQ];
__device__ float g_nll [BT];
__device__ float g_logits_fb[102926336]; // BT*VQ fallback

// ---------------- embedding ----------------
__global__ void embed_kernel(const int* __restrict__ ids,
                             const float* __restrict__ tok,
                             const float* __restrict__ pos,
                             float* __restrict__ x) {
    int i = blockIdx.x * 256 + threadIdx.x;
    if (i >= BT * DQ) return;
    int r = i / DQ, d = i - r * DQ;
    int id = ids[r];
    x[i] = tok[(size_t)id * DQ + d] + pos[(r % TQ) * DQ + d];
}

// ---------------- layernorm ----------------
__global__ void ln_kernel(const float* __restrict__ x,
                          const float* __restrict__ w,
                          const float* __restrict__ b,
                          float* __restrict__ y) {
    int row = blockIdx.x;
    const float* xr = x + (size_t)row * DQ;
    float s = 0.f, q = 0.f;
    for (int i = threadIdx.x; i < DQ; i += 256) { float v = xr[i]; s += v; q += v * v; }
    __shared__ float ss[256], sq[256];
    ss[threadIdx.x] = s; sq[threadIdx.x] = q; __syncthreads();
    for (int o = 128; o > 0; o >>= 1) {
        if (threadIdx.x < o) { ss[threadIdx.x] += ss[threadIdx.x + o]; sq[threadIdx.x] += sq[threadIdx.x + o]; }
        __syncthreads();
    }
    float mean = ss[0] * (1.f / DQ);
    float var  = sq[0] * (1.f / DQ) - mean * mean;
    float inv  = rsqrtf(var + 1e-5f);
    float* yr = y + (size_t)row * DQ;
    for (int i = threadIdx.x; i < DQ; i += 256)
        yr[i] = (xr[i] - mean) * inv * w[i] + b[i];
}

// ---------------- TF32 tensor-core GEMM ----------------
// C[M,N] = A[M,K] * B (+bias/+res/+gelu).  TRANSB: B is [N,K] (C = A*B^T).
// 128x128x16 tiles, 8 warps, warp tile 64x32 via mma.m16n8k8.tf32.
__device__ __forceinline__ uint32_t f2tf32(float x) {
    uint32_t u; asm("cvt.rna.tf32.f32 %0, %1;" : "=r"(u) : "f"(x)); return u;
}
__device__ __forceinline__ void mma8(float* c, const uint32_t* a, const uint32_t* b) {
    asm volatile("mma.sync.aligned.m16n8k8.row.col.f32.tf32.tf32.f32 "
                 "{%0,%1,%2,%3}, {%4,%5,%6,%7}, {%8,%9}, {%0,%1,%2,%3};\n"
                 : "+f"(c[0]), "+f"(c[1]), "+f"(c[2]), "+f"(c[3])
                 : "r"(a[0]), "r"(a[1]), "r"(a[2]), "r"(a[3]), "r"(b[0]), "r"(b[1]));
}

template<bool TRANSB, int EPI>   // EPI: 0 bias, 1 bias+res, 2 bias+gelu
__global__ __launch_bounds__(256)
void gemm_tf32(const float* __restrict__ A, const float* __restrict__ B,
               const float* __restrict__ bias, const float* __restrict__ res,
               float* __restrict__ C, int M, int N, int K) {
    __shared__ uint32_t As[16][132];   // [k][m], pad 4
    __shared__ uint32_t Bs[16][132];   // [k][n], pad 4

    const int tid  = threadIdx.x;
    const int lane = tid & 31, wid = tid >> 5;
    const int wm = (wid & 1) * 64, wn = (wid >> 1) * 32;
    const int g = lane >> 2, tq = lane & 3;
    const int m0 = blockIdx.y * 128, n0 = blockIdx.x * 128;

    float acc[4][4][4] = {};

    // A loader: rows ar, ar+64 ; k-cols ak..ak+3
    const int ar = tid >> 2;
    const int ak = (tid & 3) << 2;
    // B loader (no-trans): k rows bk, bk+8 ; n-cols bn..bn+3
    const int bk = tid >> 5;
    const int bn = (tid & 31) << 2;

    float4 pa0, pa1, pb0, pb1;

    auto loadA = [&](int k0) {
        pa0 = *(const float4*)(A + (size_t)(m0 + ar)      * K + k0 + ak);
        pa1 = *(const float4*)(A + (size_t)(m0 + ar + 64) * K + k0 + ak);
    };
    auto loadB = [&](int k0) {
        if (!TRANSB) {
            pb0 = *(const float4*)(B + (size_t)(k0 + bk)     * N + n0 + bn);
            pb1 = *(const float4*)(B + (size_t)(k0 + bk + 8) * N + n0 + bn);
        } else {
            int n1 = n0 + ar, n2 = n0 + ar + 64;
            pb0 = (n1 < N) ? *(const float4*)(B + (size_t)n1 * K + k0 + ak)
                           : make_float4(0.f, 0.f, 0.f, 0.f);
            pb1 = (n2 < N) ? *(const float4*)(B + (size_t)n2 * K + k0 + ak)
                           : make_float4(0.f, 0.f, 0.f, 0.f);
        }
    };
    auto storeS = [&]() {
        As[ak + 0][ar] = f2tf32(pa0.x); As[ak + 1][ar] = f2tf32(pa0.y);
        As[ak + 2][ar] = f2tf32(pa0.z); As[ak + 3][ar] = f2tf32(pa0.w);
        As[ak + 0][ar + 64] = f2tf32(pa1.x); As[ak + 1][ar + 64] = f2tf32(pa1.y);
        As[ak + 2][ar + 64] = f2tf32(pa1.z); As[ak + 3][ar + 64] = f2tf32(pa1.w);
        if (!TRANSB) {
            Bs[bk][bn + 0] = f2tf32(pb0.x); Bs[bk][bn + 1] = f2tf32(pb0.y);
            Bs[bk][bn + 2] = f2tf32(pb0.z); Bs[bk][bn + 3] = f2tf32(pb0.w);
            Bs[bk + 8][bn + 0] = f2tf32(pb1.x); Bs[bk + 8][bn + 1] = f2tf32(pb1.y);
            Bs[bk + 8][bn + 2] = f2tf32(pb1.z); Bs[bk + 8][bn + 3] = f2tf32(pb1.w);
        } else {
            Bs[ak + 0][ar] = f2tf32(pb0.x); Bs[ak + 1][ar] = f2tf32(pb0.y);
            Bs[ak + 2][ar] = f2tf32(pb0.z); Bs[ak + 3][ar] = f2tf32(pb0.w);
            Bs[ak + 0][ar + 64] = f2tf32(pb1.x); Bs[ak + 1][ar + 64] = f2tf32(pb1.y);
            Bs[ak + 2][ar + 64] = f2tf32(pb1.z); Bs[ak + 3][ar + 64] = f2tf32(pb1.w);
        }
    };

    loadA(0); loadB(0);
    for (int k0 = 0; k0 < K; k0 += 16) {
        storeS();
        __syncthreads();
        if (k0 + 16 < K) { loadA(k0 + 16); loadB(k0 + 16); }

        #pragma unroll
        for (int ks = 0; ks < 16; ks += 8) {
            uint32_t af[4][4], bf[4][2];
            #pragma unroll
            for (int mi = 0; mi < 4; mi++) {
                int m = wm + mi * 16 + g;
                af[mi][0] = As[ks + tq][m];
                af[mi][1] = As[ks + tq][m + 8];
                af[mi][2] = As[ks + tq + 4][m];
                af[mi][3] = As[ks + tq + 4][m + 8];
            }
            #pragma unroll
            for (int ni = 0; ni < 4; ni++) {
                int n = wn + ni * 8 + g;
                bf[ni][0] = Bs[ks + tq][n];
                bf[ni][1] = Bs[ks + tq + 4][n];
            }
            #pragma unroll
            for (int mi = 0; mi < 4; mi++)
                #pragma unroll
                for (int ni = 0; ni < 4; ni++)
                    mma8(acc[mi][ni], af[mi], bf[ni]);
        }
        __syncthreads();
    }

    // epilogue
    #pragma unroll
    for (int mi = 0; mi < 4; mi++) {
        #pragma unroll
        for (int ni = 0; ni < 4; ni++) {
            int m = m0 + wm + mi * 16 + g;
            int n = n0 + wn + ni * 8 + tq * 2;
            #pragma unroll
            for (int half = 0; half < 2; half++) {   // rows m, m+8
                int mm = m + half * 8;
                #pragma unroll
                for (int e = 0; e < 2; e++) {        // cols n, n+1
                    int nn = n + e;
                    if (nn >= N) continue;
                    float v = acc[mi][ni][half * 2 + e];
                    if (bias) v += bias[nn];
                    if (EPI == 1) v += res[(size_t)mm * N + nn];
                    if (EPI == 2) v = 0.5f * v * (1.f + erff(v * 0.70710678118654752440f));
                    C[(size_t)mm * N + nn] = v;
                }
            }
        }
    }
}

// ---------------- flash attention (fp32, smem-tiled) ----------------
// block = (qtile of 64, head, batch); 256 threads = 16x16 micro grid
#define AP 66                       // padded row stride
#define SMEM_ATT (3 * 64 * AP * 4)  // Qs + (Ks/Ps shared) + Vs
__global__ __launch_bounds__(256)
void flash_kernel(const float* __restrict__ qkv, float* __restrict__ out) {
    extern __shared__ float sm[];
    float* Qs = sm;                 // [64][AP]
    float* KP = sm + 64 * AP;       // K tile, then reused for P
    float* Vs = sm + 2 * 64 * AP;

    const int tid = threadIdx.x;
    const int tx = tid & 15, ty = tid >> 4;
    const int q0 = blockIdx.x * 64;
    const int h  = blockIdx.y;
    const int b  = blockIdx.z;

    // load Q tile (scaled by 1/sqrt(64))
    #pragma unroll
    for (int it = 0; it < 4; it++) {
        int q4 = tid + it * 256;            // float4 index, 0..1023
        int r = q4 >> 4, d0 = (q4 & 15) << 2;
        float4 v = *(const float4*)(qkv + (size_t)(b * TQ + q0 + r) * (3 * DQ) + h * HD + d0);
        Qs[r * AP + d0 + 0] = v.x * 0.125f;
        Qs[r * AP + d0 + 1] = v.y * 0.125f;
        Qs[r * AP + d0 + 2] = v.z * 0.125f;
        Qs[r * AP + d0 + 3] = v.w * 0.125f;
    }

    float m_[4], l_[4], o_[4][4];
    #pragma unroll
    for (int i = 0; i < 4; i++) {
        m_[i] = -1e30f; l_[i] = 0.f;
        #pragma unroll
        for (int j = 0; j < 4; j++) o_[i][j] = 0.f;
    }

    const int ktiles = q0 / 64 + 1;
    for (int kt = 0; kt < ktiles; kt++) {
        int k0 = kt * 64;
        __syncthreads();   // previous iteration's reads done before overwrite
        #pragma unroll
        for (int it = 0; it < 4; it++) {
            int q4 = tid + it * 256;
            int r = q4 >> 4, d0 = (q4 & 15) << 2;
            const float* src = qkv + (size_t)(b * TQ + k0 + r) * (3 * DQ) + h * HD + d0;
            float4 kv = *(const float4*)(src + DQ);
            float4 vv = *(const float4*)(src + 2 * DQ);
            KP[r * AP + d0 + 0] = kv.x; KP[r * AP + d0 + 1] = kv.y;
            KP[r * AP + d0 + 2] = kv.z; KP[r * AP + d0 + 3] = kv.w;
            Vs[r * AP + d0 + 0] = vv.x; Vs[r * AP + d0 + 1] = vv.y;
            Vs[r * AP + d0 + 2] = vv.z; Vs[r * AP + d0 + 3] = vv.w;
        }
        __syncthreads();

        // S = Q K^T  (thread owns rows ty*4+i, cols j*16+tx)
        float s[4][4] = {};
        #pragma unroll 8
        for (int d = 0; d < 64; d++) {
            float qv[4], kv[4];
            #pragma unroll
            for (int i = 0; i < 4; i++) qv[i] = Qs[(ty * 4 + i) * AP + d];
            #pragma unroll
            for (int j = 0; j < 4; j++) kv[j] = KP[(j * 16 + tx) * AP + d];
            #pragma unroll
            for (int i = 0; i < 4; i++)
                #pragma unroll
                for (int j = 0; j < 4; j++)
                    s[i][j] = fmaf(qv[i], kv[j], s[i][j]);
        }

        if (k0 == q0) {   // diagonal tile: causal mask
            #pragma unroll
            for (int i = 0; i < 4; i++)
                #pragma unroll
                for (int j = 0; j < 4; j++)
                    if (j * 16 + tx > ty * 4 + i) s[i][j] = -1e30f;
        }

        // online softmax per row
        #pragma unroll
        for (int i = 0; i < 4; i++) {
            float mx = fmaxf(fmaxf(s[i][0], s[i][1]), fmaxf(s[i][2], s[i][3]));
            #pragma unroll
            for (int o = 8; o > 0; o >>= 1) mx = fmaxf(mx, __shfl_xor_sync(0xffffffffu, mx, o));
            float mn = fmaxf(m_[i], mx);
            float corr = expf(m_[i] - mn);
            float rs = 0.f;
            #pragma unroll
            for (int j = 0; j < 4; j++) { s[i][j] = expf(s[i][j] - mn); rs += s[i][j]; }
            #pragma unroll
            for (int o = 8; o > 0; o >>= 1) rs += __shfl_xor_sync(0xffffffffu, rs, o);
            l_[i] = l_[i] * corr + rs;
            m_[i] = mn;
            #pragma unroll
            for (int j = 0; j < 4; j++) o_[i][j] *= corr;
        }

        __syncthreads();   // done reading K from KP
        #pragma unroll
        for (int i = 0; i < 4; i++)
            #pragma unroll
            for (int j = 0; j < 4; j++)
                KP[(ty * 4 + i) * AP + j * 16 + tx] = s[i][j];
        __syncthreads();

        // O += P V   (thread owns rows ty*4+i, dcols j*16+tx)
        #pragma unroll 8
        for (int k = 0; k < 64; k++) {
            float pv[4], vv[4];
            #pragma unroll
            for (int i = 0; i < 4; i++) pv[i] = KP[(ty * 4 + i) * AP + k];
            #pragma unroll
            for (int j = 0; j < 4; j++) vv[j] = Vs[k * AP + j * 16 + tx];
            #pragma unroll
            for (int i = 0; i < 4; i++)
                #pragma unroll
                for (int j = 0; j < 4; j++)
                    o_[i][j] = fmaf(pv[i], vv[j], o_[i][j]);
        }
    }

    #pragma unroll
    for (int i = 0; i < 4; i++) {
        float inv = 1.f / l_[i];
        #pragma unroll
        for (int j = 0; j < 4; j++)
            out[(size_t)(b * TQ + q0 + ty * 4 + i) * DQ + h * HD + j * 16 + tx] = o_[i][j] * inv;
    }
}

// ---------------- NLL / loss ----------------
__global__ void nll_kernel(const float* __restrict__ logits, const int* __restrict__ tgt,
                           float* __restrict__ nll) {
    int row = blockIdx.x;
    const float* lr = logits + (size_t)row * VQ;
    float m = -1e30f, s = 0.f;
    for (int j = threadIdx.x; j < VQ; j += 256) {
        float v = lr[j];
        if (v > m) { s = s * expf(m - v) + 1.f; m = v; }
        else       { s += expf(v - m); }
    }
    __shared__ float sm_[256], ssum[256];
    sm_[threadIdx.x] = m; ssum[threadIdx.x] = s; __syncthreads();
    for (int o = 128; o > 0; o >>= 1) {
        if (threadIdx.x < o) {
            float m2 = sm_[threadIdx.x + o], s2 = ssum[threadIdx.x + o];
            float M  = fmaxf(sm_[threadIdx.x], m2);
            ssum[threadIdx.x] = ssum[threadIdx.x] * expf(sm_[threadIdx.x] - M) + s2 * expf(m2 - M);
            sm_[threadIdx.x]  = M;
        }
        __syncthreads();
    }
    if (threadIdx.x == 0) {
        float lse = sm_[0] + logf(ssum[0]);
        int t = tgt[row];
        nll[row] = lse - lr[t];
    }
}

__global__ void loss_kernel(const float* __restrict__ nll, float* __restrict__ loss) {
    __shared__ float s[1024];
    float v = nll[threadIdx.x] + nll[threadIdx.x + 1024];
    s[threadIdx.x] = v; __syncthreads();
    for (int o = 512; o > 0; o >>= 1) {
        if (threadIdx.x < o) s[threadIdx.x] += s[threadIdx.x + o];
        __syncthreads();
    }
    if (threadIdx.x == 0) *loss = s[0] * (1.f / 2048.f);
}

// ---------------- launch ----------------
extern "C" void kernel_launch(void* const* d_in, const int* in_sizes, int n_in,
                              void* d_out, int out_size) {
    const int*   ids  = (const int*)d_in[0];
    const int*   tgt  = (const int*)d_in[1];
    const float* tok  = (const float*)d_in[2];
    const float* pos  = (const float*)d_in[3];
    const float* ln1w = (const float*)d_in[4];
    const float* ln1b = (const float*)d_in[5];
    const float* qkvw = (const float*)d_in[6];
    const float* qkvb = (const float*)d_in[7];
    const float* apw  = (const float*)d_in[8];
    const float* apb  = (const float*)d_in[9];
    const float* ln2w = (const float*)d_in[10];
    const float* ln2b = (const float*)d_in[11];
    const float* fcw  = (const float*)d_in[12];
    const float* fcb  = (const float*)d_in[13];
    const float* pw   = (const float*)d_in[14];
    const float* pb   = (const float*)d_in[15];
    const float* lnfw = (const float*)d_in[16];
    const float* lnfb = (const float*)d_in[17];

    float *x, *h, *qkv, *attn, *ffn, *nll, *lfb;
    cudaGetSymbolAddress((void**)&x,    g_x);
    cudaGetSymbolAddress((void**)&h,    g_h);
    cudaGetSymbolAddress((void**)&qkv,  g_qkv);
    cudaGetSymbolAddress((void**)&attn, g_attn);
    cudaGetSymbolAddress((void**)&ffn,  g_ffn);
    cudaGetSymbolAddress((void**)&nll,  g_nll);
    cudaGetSymbolAddress((void**)&lfb,  g_logits_fb);

    cudaFuncSetAttribute(flash_kernel, cudaFuncAttributeMaxDynamicSharedMemorySize, SMEM_ATT);

    const long long LOGN = (long long)BT * VQ;
    float* out    = (float*)d_out;
    float* logits;
    float* lossp  = nullptr;
    if ((long long)out_size > LOGN) {
        lossp  = out;
        logits = out + ((long long)out_size - LOGN);
    } else if ((long long)out_size == LOGN) {
        logits = out;
    } else {
        lossp  = out;
        logits = lfb;
    }

    embed_kernel<<<(BT * DQ + 255) / 256, 256>>>(ids, tok, pos, x);

    for (int l = 0; l < LQ; l++) {
        ln_kernel<<<BT, 256>>>(x, ln1w + l * DQ, ln1b + l * DQ, h);
        gemm_tf32<false, 0><<<dim3((3 * DQ) / 128, BT / 128), 256>>>(
            h, qkvw + (size_t)l * DQ * 3 * DQ, qkvb + l * 3 * DQ, nullptr, qkv, BT, 3 * DQ, DQ);
        flash_kernel<<<dim3(TQ / 64, HQ, BQ), 256, SMEM_ATT>>>(qkv, attn);
        gemm_tf32<false, 1><<<dim3(DQ / 128, BT / 128), 256>>>(
            attn, apw + (size_t)l * DQ * DQ, apb + l * DQ, x, x, BT, DQ, DQ);
        ln_kernel<<<BT, 256>>>(x, ln2w + l * DQ, ln2b + l * DQ, h);
        gemm_tf32<false, 2><<<dim3((4 * DQ) / 128, BT / 128), 256>>>(
            h, fcw + (size_t)l * DQ * 4 * DQ, fcb + l * 4 * DQ, nullptr, ffn, BT, 4 * DQ, DQ);
        gemm_tf32<false, 1><<<dim3(DQ / 128, BT / 128), 256>>>(
            ffn, pw + (size_t)l * 4 * DQ * DQ, pb + l * DQ, x, x, BT, DQ, 4 * DQ);
    }

    ln_kernel<<<BT, 256>>>(x, lnfw, lnfb, h);
    gemm_tf32<true, 0><<<dim3((VQ + 127) / 128, BT / 128), 256>>>(
        h, tok, nullptr, nullptr, logits, BT, VQ, DQ);

    if (lossp) {
        nll_kernel<<<BT, 256>>>(logits, tgt, nll);
        loss_kernel<<<1, 1024>>>(nll, lossp);
    }
}

// round 3
// speedup vs baseline: 4.8864x; 1.2885x over previous
#include <cuda_runtime.h>
#include <math.h>
#include <stdint.h>

// ---------------- problem constants ----------------
#define BQ 2
#define TQ 1024
#define DQ 768
#define LQ 4
#define HQ 12
#define VQ 50257
#define BT (BQ*TQ)
#define HD 64

// ---------------- scratch ----------------
__device__ float g_x   [BT*DQ];
__device__ float g_h   [BT*DQ];
__device__ float g_qkv [BT*3*DQ];
__device__ float g_attn[BT*DQ];
__device__ float g_ffn [BT*4*DQ];
__device__ float g_nll [BT];
__device__ float g_logits_fb[102926336];

// ---------------- embedding ----------------
__global__ void embed_kernel(const int* __restrict__ ids,
                             const float* __restrict__ tok,
                             const float* __restrict__ pos,
                             float* __restrict__ x) {
    int i = blockIdx.x * 256 + threadIdx.x;
    if (i >= BT * DQ) return;
    int r = i / DQ, d = i - r * DQ;
    int id = ids[r];
    x[i] = tok[(size_t)id * DQ + d] + pos[(r % TQ) * DQ + d];
}

// ---------------- layernorm ----------------
__global__ void ln_kernel(const float* __restrict__ x,
                          const float* __restrict__ w,
                          const float* __restrict__ b,
                          float* __restrict__ y) {
    int row = blockIdx.x;
    const float* xr = x + (size_t)row * DQ;
    float s = 0.f, q = 0.f;
    for (int i = threadIdx.x; i < DQ; i += 256) { float v = xr[i]; s += v; q += v * v; }
    __shared__ float ss[256], sq[256];
    ss[threadIdx.x] = s; sq[threadIdx.x] = q; __syncthreads();
    for (int o = 128; o > 0; o >>= 1) {
        if (threadIdx.x < o) { ss[threadIdx.x] += ss[threadIdx.x + o]; sq[threadIdx.x] += sq[threadIdx.x + o]; }
        __syncthreads();
    }
    float mean = ss[0] * (1.f / DQ);
    float var  = sq[0] * (1.f / DQ) - mean * mean;
    float inv  = rsqrtf(var + 1e-5f);
    float* yr = y + (size_t)row * DQ;
    for (int i = threadIdx.x; i < DQ; i += 256)
        yr[i] = (xr[i] - mean) * inv * w[i] + b[i];
}

// ---------------- TF32 tensor-core GEMM, cp.async double-buffered ----------------
__device__ __forceinline__ uint32_t f2tf32(float x) {
    uint32_t u; asm("cvt.rna.tf32.f32 %0, %1;" : "=r"(u) : "f"(x)); return u;
}
__device__ __forceinline__ void mma8(float* c, const uint32_t* a, const uint32_t* b) {
    asm volatile("mma.sync.aligned.m16n8k8.row.col.f32.tf32.tf32.f32 "
                 "{%0,%1,%2,%3}, {%4,%5,%6,%7}, {%8,%9}, {%0,%1,%2,%3};\n"
                 : "+f"(c[0]), "+f"(c[1]), "+f"(c[2]), "+f"(c[3])
                 : "r"(a[0]), "r"(a[1]), "r"(a[2]), "r"(a[3]), "r"(b[0]), "r"(b[1]));
}
__device__ __forceinline__ void cpa16(uint32_t dst, const void* src) {
    asm volatile("cp.async.cg.shared.global [%0], [%1], 16;\n" :: "r"(dst), "l"(src));
}
__device__ __forceinline__ void cpa16z(uint32_t dst, const void* src, int bytes) {
    asm volatile("cp.async.cg.shared.global [%0], [%1], 16, %2;\n" :: "r"(dst), "l"(src), "r"(bytes));
}

// BM=BN=128, BK=32, 2 stages. A stride 36, B(nt) stride 136, B(t) stride 36.
#define GA_STRIDE 36
#define GB_STRIDE 136
#define SMEM_A_FLOATS (2*128*GA_STRIDE)          // 9216
#define SMEM_GEMM ((SMEM_A_FLOATS + 9216) * 4)   // 73728 bytes

template<bool TRANSB, int EPI>   // EPI: 0 bias, 1 bias+res, 2 bias+gelu
__global__ __launch_bounds__(256)
void gemm_tf32(const float* __restrict__ A, const float* __restrict__ B,
               const float* __restrict__ bias, const float* __restrict__ res,
               float* __restrict__ C, int M, int N, int K) {
    extern __shared__ float sm[];
    float* As = sm;                    // [2][128][36]
    float* Bs = sm + SMEM_A_FLOATS;    // nt: [2][32][136]  t: [2][128][36]

    const int tid  = threadIdx.x;
    const int lane = tid & 31, wid = tid >> 5;
    const int wm = (wid & 1) * 64, wn = (wid >> 1) * 32;
    const int g = lane >> 2, tq = lane & 3;

    int m0, n0;
    if (TRANSB) { m0 = blockIdx.x * 128; n0 = blockIdx.y * 128; }
    else        { m0 = blockIdx.y * 128; n0 = blockIdx.x * 128; }

    const uint32_t sA = (uint32_t)__cvta_generic_to_shared(As);
    const uint32_t sB = (uint32_t)__cvta_generic_to_shared(Bs);

    // A loader: thread -> (row = tid>>3 (+32*it), col4 = (tid&7)*4)
    const int arow = tid >> 3, acol = (tid & 7) << 2;
    // B nt loader: (k = tid>>5 (+8*it), n4 = (tid&31)*4)
    const int bk = tid >> 5, bn = (tid & 31) << 2;

    auto load_tile = [&](int t) {
        int k0 = t * 32, st = t & 1;
        #pragma unroll
        for (int it = 0; it < 4; it++) {
            int r = arow + it * 32;
            cpa16(sA + ((st * 128 + r) * GA_STRIDE + acol) * 4,
                  A + (size_t)(m0 + r) * K + k0 + acol);
        }
        if (!TRANSB) {
            #pragma unroll
            for (int it = 0; it < 4; it++) {
                int r = bk + it * 8;
                cpa16(sB + ((st * 32 + r) * GB_STRIDE + bn) * 4,
                      B + (size_t)(k0 + r) * N + n0 + bn);
            }
        } else {
            #pragma unroll
            for (int it = 0; it < 4; it++) {
                int r = arow + it * 32;
                int n = n0 + r;
                int ok = (n < N);
                cpa16z(sB + ((st * 128 + r) * GA_STRIDE + acol) * 4,
                       B + (size_t)(ok ? n : (N - 1)) * K + k0 + acol, ok ? 16 : 0);
            }
        }
    };

    float acc[4][4][4] = {};

    load_tile(0);
    asm volatile("cp.async.commit_group;\n");
    const int nt = K / 32;
    for (int t = 0; t < nt; t++) {
        if (t + 1 < nt) load_tile(t + 1);
        asm volatile("cp.async.commit_group;\n");
        asm volatile("cp.async.wait_group 1;\n");
        __syncthreads();

        const int st = t & 1;
        const float* Ab = As + st * 128 * GA_STRIDE;
        #pragma unroll
        for (int ks = 0; ks < 4; ks++) {
            int k = ks * 8 + tq;
            uint32_t af[4][4], bf[4][2];
            #pragma unroll
            for (int mi = 0; mi < 4; mi++) {
                int m = wm + mi * 16 + g;
                af[mi][0] = f2tf32(Ab[m * GA_STRIDE + k]);
                af[mi][1] = f2tf32(Ab[(m + 8) * GA_STRIDE + k]);
                af[mi][2] = f2tf32(Ab[m * GA_STRIDE + k + 4]);
                af[mi][3] = f2tf32(Ab[(m + 8) * GA_STRIDE + k + 4]);
            }
            if (!TRANSB) {
                const float* Bb = Bs + st * 32 * GB_STRIDE;
                #pragma unroll
                for (int ni = 0; ni < 4; ni++) {
                    int n = wn + ni * 8 + g;
                    bf[ni][0] = f2tf32(Bb[k * GB_STRIDE + n]);
                    bf[ni][1] = f2tf32(Bb[(k + 4) * GB_STRIDE + n]);
                }
            } else {
                const float* Bb = Bs + st * 128 * GA_STRIDE;
                #pragma unroll
                for (int ni = 0; ni < 4; ni++) {
                    int n = wn + ni * 8 + g;
                    bf[ni][0] = f2tf32(Bb[n * GA_STRIDE + k]);
                    bf[ni][1] = f2tf32(Bb[n * GA_STRIDE + k + 4]);
                }
            }
            #pragma unroll
            for (int mi = 0; mi < 4; mi++)
                #pragma unroll
                for (int ni = 0; ni < 4; ni++)
                    mma8(acc[mi][ni], af[mi], bf[ni]);
        }
        __syncthreads();
    }

    // epilogue
    #pragma unroll
    for (int mi = 0; mi < 4; mi++) {
        #pragma unroll
        for (int ni = 0; ni < 4; ni++) {
            int m = m0 + wm + mi * 16 + g;
            int n = n0 + wn + ni * 8 + tq * 2;
            #pragma unroll
            for (int half = 0; half < 2; half++) {
                int mm = m + half * 8;
                #pragma unroll
                for (int e = 0; e < 2; e++) {
                    int nn = n + e;
                    if (TRANSB && nn >= N) continue;
                    float v = acc[mi][ni][half * 2 + e];
                    if (bias) v += bias[nn];
                    if (EPI == 1) v += res[(size_t)mm * N + nn];
                    if (EPI == 2) v = 0.5f * v * (1.f + erff(v * 0.70710678118654752440f));
                    C[(size_t)mm * N + nn] = v;
                }
            }
        }
    }
}

// ---------------- flash attention (fp32, smem-tiled) ----------------
#define AP 66
#define SMEM_ATT (3 * 64 * AP * 4)
__global__ __launch_bounds__(256)
void flash_kernel(const float* __restrict__ qkv, float* __restrict__ out) {
    extern __shared__ float sm[];
    float* Qs = sm;
    float* KP = sm + 64 * AP;
    float* Vs = sm + 2 * 64 * AP;

    const int tid = threadIdx.x;
    const int tx = tid & 15, ty = tid >> 4;
    const int q0 = blockIdx.x * 64;
    const int h  = blockIdx.y;
    const int b  = blockIdx.z;

    #pragma unroll
    for (int it = 0; it < 4; it++) {
        int q4 = tid + it * 256;
        int r = q4 >> 4, d0 = (q4 & 15) << 2;
        float4 v = *(const float4*)(qkv + (size_t)(b * TQ + q0 + r) * (3 * DQ) + h * HD + d0);
        Qs[r * AP + d0 + 0] = v.x * 0.125f;
        Qs[r * AP + d0 + 1] = v.y * 0.125f;
        Qs[r * AP + d0 + 2] = v.z * 0.125f;
        Qs[r * AP + d0 + 3] = v.w * 0.125f;
    }

    float m_[4], l_[4], o_[4][4];
    #pragma unroll
    for (int i = 0; i < 4; i++) {
        m_[i] = -1e30f; l_[i] = 0.f;
        #pragma unroll
        for (int j = 0; j < 4; j++) o_[i][j] = 0.f;
    }

    const int ktiles = q0 / 64 + 1;
    for (int kt = 0; kt < ktiles; kt++) {
        int k0 = kt * 64;
        __syncthreads();
        #pragma unroll
        for (int it = 0; it < 4; it++) {
            int q4 = tid + it * 256;
            int r = q4 >> 4, d0 = (q4 & 15) << 2;
            const float* src = qkv + (size_t)(b * TQ + k0 + r) * (3 * DQ) + h * HD + d0;
            float4 kv = *(const float4*)(src + DQ);
            float4 vv = *(const float4*)(src + 2 * DQ);
            KP[r * AP + d0 + 0] = kv.x; KP[r * AP + d0 + 1] = kv.y;
            KP[r * AP + d0 + 2] = kv.z; KP[r * AP + d0 + 3] = kv.w;
            Vs[r * AP + d0 + 0] = vv.x; Vs[r * AP + d0 + 1] = vv.y;
            Vs[r * AP + d0 + 2] = vv.z; Vs[r * AP + d0 + 3] = vv.w;
        }
        __syncthreads();

        float s[4][4] = {};
        #pragma unroll 8
        for (int d = 0; d < 64; d++) {
            float qv[4], kv[4];
            #pragma unroll
            for (int i = 0; i < 4; i++) qv[i] = Qs[(ty * 4 + i) * AP + d];
            #pragma unroll
            for (int j = 0; j < 4; j++) kv[j] = KP[(j * 16 + tx) * AP + d];
            #pragma unroll
            for (int i = 0; i < 4; i++)
                #pragma unroll
                for (int j = 0; j < 4; j++)
                    s[i][j] = fmaf(qv[i], kv[j], s[i][j]);
        }

        if (k0 == q0) {
            #pragma unroll
            for (int i = 0; i < 4; i++)
                #pragma unroll
                for (int j = 0; j < 4; j++)
                    if (j * 16 + tx > ty * 4 + i) s[i][j] = -1e30f;
        }

        #pragma unroll
        for (int i = 0; i < 4; i++) {
            float mx = fmaxf(fmaxf(s[i][0], s[i][1]), fmaxf(s[i][2], s[i][3]));
            #pragma unroll
            for (int o = 8; o > 0; o >>= 1) mx = fmaxf(mx, __shfl_xor_sync(0xffffffffu, mx, o));
            float mn = fmaxf(m_[i], mx);
            float corr = __expf(m_[i] - mn);
            float rs = 0.f;
            #pragma unroll
            for (int j = 0; j < 4; j++) { s[i][j] = __expf(s[i][j] - mn); rs += s[i][j]; }
            #pragma unroll
            for (int o = 8; o > 0; o >>= 1) rs += __shfl_xor_sync(0xffffffffu, rs, o);
            l_[i] = l_[i] * corr + rs;
            m_[i] = mn;
            #pragma unroll
            for (int j = 0; j < 4; j++) o_[i][j] *= corr;
        }

        __syncthreads();
        #pragma unroll
        for (int i = 0; i < 4; i++)
            #pragma unroll
            for (int j = 0; j < 4; j++)
                KP[(ty * 4 + i) * AP + j * 16 + tx] = s[i][j];
        __syncthreads();

        #pragma unroll 8
        for (int k = 0; k < 64; k++) {
            float pv[4], vv[4];
            #pragma unroll
            for (int i = 0; i < 4; i++) pv[i] = KP[(ty * 4 + i) * AP + k];
            #pragma unroll
            for (int j = 0; j < 4; j++) vv[j] = Vs[k * AP + j * 16 + tx];
            #pragma unroll
            for (int i = 0; i < 4; i++)
                #pragma unroll
                for (int j = 0; j < 4; j++)
                    o_[i][j] = fmaf(pv[i], vv[j], o_[i][j]);
        }
    }

    #pragma unroll
    for (int i = 0; i < 4; i++) {
        float inv = 1.f / l_[i];
        #pragma unroll
        for (int j = 0; j < 4; j++)
            out[(size_t)(b * TQ + q0 + ty * 4 + i) * DQ + h * HD + j * 16 + tx] = o_[i][j] * inv;
    }
}

// ---------------- NLL / loss ----------------
__global__ void nll_kernel(const float* __restrict__ logits, const int* __restrict__ tgt,
                           float* __restrict__ nll) {
    int row = blockIdx.x;
    const float* lr = logits + (size_t)row * VQ;
    float m = -1e30f, s = 0.f;
    for (int j = threadIdx.x; j < VQ; j += 256) {
        float v = lr[j];
        if (v > m) { s = s * expf(m - v) + 1.f; m = v; }
        else       { s += expf(v - m); }
    }
    __shared__ float sm_[256], ssum[256];
    sm_[threadIdx.x] = m; ssum[threadIdx.x] = s; __syncthreads();
    for (int o = 128; o > 0; o >>= 1) {
        if (threadIdx.x < o) {
            float m2 = sm_[threadIdx.x + o], s2 = ssum[threadIdx.x + o];
            float M  = fmaxf(sm_[threadIdx.x], m2);
            ssum[threadIdx.x] = ssum[threadIdx.x] * expf(sm_[threadIdx.x] - M) + s2 * expf(m2 - M);
            sm_[threadIdx.x]  = M;
        }
        __syncthreads();
    }
    if (threadIdx.x == 0) {
        float lse = sm_[0] + logf(ssum[0]);
        int t = tgt[row];
        nll[row] = lse - lr[t];
    }
}

__global__ void loss_kernel(const float* __restrict__ nll, float* __restrict__ loss) {
    __shared__ float s[1024];
    float v = nll[threadIdx.x] + nll[threadIdx.x + 1024];
    s[threadIdx.x] = v; __syncthreads();
    for (int o = 512; o > 0; o >>= 1) {
        if (threadIdx.x < o) s[threadIdx.x] += s[threadIdx.x + o];
        __syncthreads();
    }
    if (threadIdx.x == 0) *loss = s[0] * (1.f / 2048.f);
}

// ---------------- launch ----------------
extern "C" void kernel_launch(void* const* d_in, const int* in_sizes, int n_in,
                              void* d_out, int out_size) {
    const int*   ids  = (const int*)d_in[0];
    const int*   tgt  = (const int*)d_in[1];
    const float* tok  = (const float*)d_in[2];
    const float* pos  = (const float*)d_in[3];
    const float* ln1w = (const float*)d_in[4];
    const float* ln1b = (const float*)d_in[5];
    const float* qkvw = (const float*)d_in[6];
    const float* qkvb = (const float*)d_in[7];
    const float* apw  = (const float*)d_in[8];
    const float* apb  = (const float*)d_in[9];
    const float* ln2w = (const float*)d_in[10];
    const float* ln2b = (const float*)d_in[11];
    const float* fcw  = (const float*)d_in[12];
    const float* fcb  = (const float*)d_in[13];
    const float* pw   = (const float*)d_in[14];
    const float* pb   = (const float*)d_in[15];
    const float* lnfw = (const float*)d_in[16];
    const float* lnfb = (const float*)d_in[17];

    float *x, *h, *qkv, *attn, *ffn, *nll, *lfb;
    cudaGetSymbolAddress((void**)&x,    g_x);
    cudaGetSymbolAddress((void**)&h,    g_h);
    cudaGetSymbolAddress((void**)&qkv,  g_qkv);
    cudaGetSymbolAddress((void**)&attn, g_attn);
    cudaGetSymbolAddress((void**)&ffn,  g_ffn);
    cudaGetSymbolAddress((void**)&nll,  g_nll);
    cudaGetSymbolAddress((void**)&lfb,  g_logits_fb);

    cudaFuncSetAttribute(flash_kernel, cudaFuncAttributeMaxDynamicSharedMemorySize, SMEM_ATT);
    cudaFuncSetAttribute(gemm_tf32<false,0>, cudaFuncAttributeMaxDynamicSharedMemorySize, SMEM_GEMM);
    cudaFuncSetAttribute(gemm_tf32<false,1>, cudaFuncAttributeMaxDynamicSharedMemorySize, SMEM_GEMM);
    cudaFuncSetAttribute(gemm_tf32<false,2>, cudaFuncAttributeMaxDynamicSharedMemorySize, SMEM_GEMM);
    cudaFuncSetAttribute(gemm_tf32<true,0>,  cudaFuncAttributeMaxDynamicSharedMemorySize, SMEM_GEMM);

    const long long LOGN = (long long)BT * VQ;
    float* out    = (float*)d_out;
    float* logits;
    float* lossp  = nullptr;
    if ((long long)out_size > LOGN) {
        lossp  = out;
        logits = out + ((long long)out_size - LOGN);
    } else if ((long long)out_size == LOGN) {
        logits = out;
    } else {
        lossp  = out;
        logits = lfb;
    }

    embed_kernel<<<(BT * DQ + 255) / 256, 256>>>(ids, tok, pos, x);

    for (int l = 0; l < LQ; l++) {
        ln_kernel<<<BT, 256>>>(x, ln1w + l * DQ, ln1b + l * DQ, h);
        gemm_tf32<false, 0><<<dim3((3 * DQ) / 128, BT / 128), 256, SMEM_GEMM>>>(
            h, qkvw + (size_t)l * DQ * 3 * DQ, qkvb + l * 3 * DQ, nullptr, qkv, BT, 3 * DQ, DQ);
        flash_kernel<<<dim3(TQ / 64, HQ, BQ), 256, SMEM_ATT>>>(qkv, attn);
        gemm_tf32<false, 1><<<dim3(DQ / 128, BT / 128), 256, SMEM_GEMM>>>(
            attn, apw + (size_t)l * DQ * DQ, apb + l * DQ, x, x, BT, DQ, DQ);
        ln_kernel<<<BT, 256>>>(x, ln2w + l * DQ, ln2b + l * DQ, h);
        gemm_tf32<false, 2><<<dim3((4 * DQ) / 128, BT / 128), 256, SMEM_GEMM>>>(
            h, fcw + (size_t)l * DQ * 4 * DQ, fcb + l * 4 * DQ, nullptr, ffn, BT, 4 * DQ, DQ);
        gemm_tf32<false, 1><<<dim3(DQ / 128, BT / 128), 256, SMEM_GEMM>>>(
            ffn, pw + (size_t)l * 4 * DQ * DQ, pb + l * DQ, x, x, BT, DQ, 4 * DQ);
    }

    ln_kernel<<<BT, 256>>>(x, lnfw, lnfb, h);
    // TRANSB: grid.x = M tiles, grid.y = N tiles (keeps A + B-slice L2-resident)
    gemm_tf32<true, 0><<<dim3(BT / 128, (VQ + 127) / 128), 256, SMEM_GEMM>>>(
        h, tok, nullptr, nullptr, logits, BT, VQ, DQ);

    if (lossp) {
        nll_kernel<<<BT, 256>>>(logits, tgt, nll);
        loss_kernel<<<1, 1024>>>(nll, lossp);
    }
}

// round 4
// speedup vs baseline: 5.1985x; 1.0639x over previous
#include <cuda_runtime.h>
#include <math.h>
#include <stdint.h>

// ---------------- problem constants ----------------
#define BQ 2
#define TQ 1024
#define DQ 768
#define LQ 4
#define HQ 12
#define VQ 50257
#define BT (BQ*TQ)
#define HD 64

// ---------------- scratch ----------------
__device__ float g_x   [BT*DQ];
__device__ float g_h   [BT*DQ];
__device__ float g_qkv [BT*3*DQ];
__device__ float g_attn[BT*DQ];
__device__ float g_ffn [BT*4*DQ];
__device__ float g_nll [BT];
__device__ float g_logits_fb[102926336];
// tf32-rounded weight copies
__device__ float g_wqkv[LQ*DQ*3*DQ];   // 7,077,888
__device__ float g_wap [LQ*DQ*DQ];     // 2,359,296
__device__ float g_wfc [LQ*DQ*4*DQ];   // 9,437,184
__device__ float g_wpr [LQ*4*DQ*DQ];   // 9,437,184
__device__ float g_tokt[(size_t)VQ*DQ];// 38,597,376

__device__ __forceinline__ uint32_t f2tf32(float x) {
    uint32_t u; asm("cvt.rna.tf32.f32 %0, %1;" : "=r"(u) : "f"(x)); return u;
}
__device__ __forceinline__ float rtf32(float x) { return __uint_as_float(f2tf32(x)); }

// ---------------- tf32 pre-round (float4) ----------------
__global__ void cvt_kernel(const float4* __restrict__ src, float4* __restrict__ dst, int n4) {
    int i = blockIdx.x * 256 + threadIdx.x;
    if (i >= n4) return;
    float4 v = src[i];
    v.x = rtf32(v.x); v.y = rtf32(v.y); v.z = rtf32(v.z); v.w = rtf32(v.w);
    dst[i] = v;
}

// ---------------- embedding ----------------
__global__ void embed_kernel(const int* __restrict__ ids,
                             const float* __restrict__ tok,
                             const float* __restrict__ pos,
                             float* __restrict__ x) {
    int i = blockIdx.x * 256 + threadIdx.x;
    if (i >= BT * DQ) return;
    int r = i / DQ, d = i - r * DQ;
    int id = ids[r];
    x[i] = tok[(size_t)id * DQ + d] + pos[(r % TQ) * DQ + d];
}

// ---------------- layernorm (rounds output to tf32: feeds GEMM A) ----------------
__global__ void ln_kernel(const float* __restrict__ x,
                          const float* __restrict__ w,
                          const float* __restrict__ b,
                          float* __restrict__ y) {
    int row = blockIdx.x;
    const float* xr = x + (size_t)row * DQ;
    float s = 0.f, q = 0.f;
    for (int i = threadIdx.x; i < DQ; i += 256) { float v = xr[i]; s += v; q += v * v; }
    __shared__ float ss[256], sq[256];
    ss[threadIdx.x] = s; sq[threadIdx.x] = q; __syncthreads();
    for (int o = 128; o > 0; o >>= 1) {
        if (threadIdx.x < o) { ss[threadIdx.x] += ss[threadIdx.x + o]; sq[threadIdx.x] += sq[threadIdx.x + o]; }
        __syncthreads();
    }
    float mean = ss[0] * (1.f / DQ);
    float var  = sq[0] * (1.f / DQ) - mean * mean;
    float inv  = rsqrtf(var + 1e-5f);
    float* yr = y + (size_t)row * DQ;
    for (int i = threadIdx.x; i < DQ; i += 256)
        yr[i] = rtf32((xr[i] - mean) * inv * w[i] + b[i]);
}

// ---------------- TF32 GEMM, cp.async 3-stage, no in-loop cvt ----------------
__device__ __forceinline__ void mma8(float* c, const uint32_t* a, const uint32_t* b) {
    asm volatile("mma.sync.aligned.m16n8k8.row.col.f32.tf32.tf32.f32 "
                 "{%0,%1,%2,%3}, {%4,%5,%6,%7}, {%8,%9}, {%0,%1,%2,%3};\n"
                 : "+f"(c[0]), "+f"(c[1]), "+f"(c[2]), "+f"(c[3])
                 : "r"(a[0]), "r"(a[1]), "r"(a[2]), "r"(a[3]), "r"(b[0]), "r"(b[1]));
}
__device__ __forceinline__ void cpa16(uint32_t dst, const void* src) {
    asm volatile("cp.async.cg.shared.global [%0], [%1], 16;\n" :: "r"(dst), "l"(src));
}
__device__ __forceinline__ void cpa16z(uint32_t dst, const void* src, int bytes) {
    asm volatile("cp.async.cg.shared.global [%0], [%1], 16, %2;\n" :: "r"(dst), "l"(src), "r"(bytes));
}

#define GA_STRIDE 36
#define GB_STRIDE 136
#define NSTAGE 3
#define SMEM_A_FLOATS (NSTAGE*128*GA_STRIDE)               // 13824
#define SMEM_GEMM ((SMEM_A_FLOATS + NSTAGE*128*GA_STRIDE) * 4)  // 110592 bytes

template<bool TRANSB, int EPI>   // EPI: 0 bias, 1 bias+res, 2 bias+gelu(round tf32)
__global__ __launch_bounds__(256)
void gemm_tf32(const float* __restrict__ A, const float* __restrict__ B,
               const float* __restrict__ bias, const float* __restrict__ res,
               float* __restrict__ C, int M, int N, int K) {
    extern __shared__ float sm[];
    float* As = sm;
    float* Bs = sm + SMEM_A_FLOATS;

    const int tid  = threadIdx.x;
    const int lane = tid & 31, wid = tid >> 5;
    const int wm = (wid & 1) * 64, wn = (wid >> 1) * 32;
    const int g = lane >> 2, tq = lane & 3;

    int m0, n0;
    if (TRANSB) { m0 = blockIdx.x * 128; n0 = blockIdx.y * 128; }
    else        { m0 = blockIdx.y * 128; n0 = blockIdx.x * 128; }

    const uint32_t sA = (uint32_t)__cvta_generic_to_shared(As);
    const uint32_t sB = (uint32_t)__cvta_generic_to_shared(Bs);

    const int arow = tid >> 3, acol = (tid & 7) << 2;
    const int bk = tid >> 5, bn = (tid & 31) << 2;

    auto load_tile = [&](int t) {
        int k0 = t * 32, st = t % NSTAGE;
        #pragma unroll
        for (int it = 0; it < 4; it++) {
            int r = arow + it * 32;
            cpa16(sA + ((st * 128 + r) * GA_STRIDE + acol) * 4,
                  A + (size_t)(m0 + r) * K + k0 + acol);
        }
        if (!TRANSB) {
            #pragma unroll
            for (int it = 0; it < 4; it++) {
                int r = bk + it * 8;
                cpa16(sB + ((st * 32 + r) * GB_STRIDE + bn) * 4,
                      B + (size_t)(k0 + r) * N + n0 + bn);
            }
        } else {
            #pragma unroll
            for (int it = 0; it < 4; it++) {
                int r = arow + it * 32;
                int n = n0 + r;
                int ok = (n < N);
                cpa16z(sB + ((st * 128 + r) * GA_STRIDE + acol) * 4,
                       B + (size_t)(ok ? n : (N - 1)) * K + k0 + acol, ok ? 16 : 0);
            }
        }
    };

    float acc[4][4][4] = {};
    const int nt = K / 32;

    load_tile(0);
    asm volatile("cp.async.commit_group;\n");
    load_tile(1);
    asm volatile("cp.async.commit_group;\n");

    for (int t = 0; t < nt; t++) {
        if (t + 2 < nt) load_tile(t + 2);
        asm volatile("cp.async.commit_group;\n");
        asm volatile("cp.async.wait_group 2;\n");
        __syncthreads();

        const int st = t % NSTAGE;
        const float* Ab = As + st * 128 * GA_STRIDE;
        #pragma unroll
        for (int ks = 0; ks < 4; ks++) {
            int k = ks * 8 + tq;
            uint32_t af[4][4], bf[4][2];
            #pragma unroll
            for (int mi = 0; mi < 4; mi++) {
                int m = wm + mi * 16 + g;
                af[mi][0] = __float_as_uint(Ab[m * GA_STRIDE + k]);
                af[mi][1] = __float_as_uint(Ab[(m + 8) * GA_STRIDE + k]);
                af[mi][2] = __float_as_uint(Ab[m * GA_STRIDE + k + 4]);
                af[mi][3] = __float_as_uint(Ab[(m + 8) * GA_STRIDE + k + 4]);
            }
            if (!TRANSB) {
                const float* Bb = Bs + st * 32 * GB_STRIDE;
                #pragma unroll
                for (int ni = 0; ni < 4; ni++) {
                    int n = wn + ni * 8 + g;
                    bf[ni][0] = __float_as_uint(Bb[k * GB_STRIDE + n]);
                    bf[ni][1] = __float_as_uint(Bb[(k + 4) * GB_STRIDE + n]);
                }
            } else {
                const float* Bb = Bs + st * 128 * GA_STRIDE;
                #pragma unroll
                for (int ni = 0; ni < 4; ni++) {
                    int n = wn + ni * 8 + g;
                    bf[ni][0] = __float_as_uint(Bb[n * GA_STRIDE + k]);
                    bf[ni][1] = __float_as_uint(Bb[n * GA_STRIDE + k + 4]);
                }
            }
            #pragma unroll
            for (int mi = 0; mi < 4; mi++)
                #pragma unroll
                for (int ni = 0; ni < 4; ni++)
                    mma8(acc[mi][ni], af[mi], bf[ni]);
        }
        __syncthreads();
    }

    #pragma unroll
    for (int mi = 0; mi < 4; mi++) {
        #pragma unroll
        for (int ni = 0; ni < 4; ni++) {
            int m = m0 + wm + mi * 16 + g;
            int n = n0 + wn + ni * 8 + tq * 2;
            #pragma unroll
            for (int half = 0; half < 2; half++) {
                int mm = m + half * 8;
                #pragma unroll
                for (int e = 0; e < 2; e++) {
                    int nn = n + e;
                    if (TRANSB && nn >= N) continue;
                    float v = acc[mi][ni][half * 2 + e];
                    if (bias) v += bias[nn];
                    if (EPI == 1) v += res[(size_t)mm * N + nn];
                    if (EPI == 2) {
                        v = 0.5f * v * (1.f + erff(v * 0.70710678118654752440f));
                        v = rtf32(v);
                    }
                    C[(size_t)mm * N + nn] = v;
                }
            }
        }
    }
}

// ---------------- flash attention (fp32, vectorized smem) ----------------
#define AP 68
#define SMEM_ATT (3 * 64 * AP * 4)   // 52224
__global__ __launch_bounds__(256)
void flash_kernel(const float* __restrict__ qkv, float* __restrict__ out) {
    extern __shared__ float sm[];
    float* Qs = sm;                 // [64][AP]
    float* KP = sm + 64 * AP;       // K tile, then P
    float* Vs = sm + 2 * 64 * AP;

    const int tid = threadIdx.x;
    const int tx = tid & 15, ty = tid >> 4;
    const int q0 = blockIdx.x * 64;
    const int h  = blockIdx.y;
    const int b  = blockIdx.z;

    #pragma unroll
    for (int it = 0; it < 4; it++) {
        int q4 = tid + it * 256;
        int r = q4 >> 4, d0 = (q4 & 15) << 2;
        float4 v = *(const float4*)(qkv + (size_t)(b * TQ + q0 + r) * (3 * DQ) + h * HD + d0);
        v.x *= 0.125f; v.y *= 0.125f; v.z *= 0.125f; v.w *= 0.125f;
        *(float4*)(Qs + r * AP + d0) = v;
    }

    float m_[4], l_[4], o_[4][4];
    #pragma unroll
    for (int i = 0; i < 4; i++) {
        m_[i] = -1e30f; l_[i] = 0.f;
        #pragma unroll
        for (int j = 0; j < 4; j++) o_[i][j] = 0.f;
    }

    const int ktiles = q0 / 64 + 1;
    for (int kt = 0; kt < ktiles; kt++) {
        int k0 = kt * 64;
        __syncthreads();
        #pragma unroll
        for (int it = 0; it < 4; it++) {
            int q4 = tid + it * 256;
            int r = q4 >> 4, d0 = (q4 & 15) << 2;
            const float* src = qkv + (size_t)(b * TQ + k0 + r) * (3 * DQ) + h * HD + d0;
            float4 kv = *(const float4*)(src + DQ);
            float4 vv = *(const float4*)(src + 2 * DQ);
            *(float4*)(KP + r * AP + d0) = kv;
            *(float4*)(Vs + r * AP + d0) = vv;
        }
        __syncthreads();

        // S = Q K^T : vectorized over d
        float s[4][4] = {};
        #pragma unroll 4
        for (int d = 0; d < 64; d += 4) {
            float4 qv[4], kv[4];
            #pragma unroll
            for (int i = 0; i < 4; i++) qv[i] = *(const float4*)(Qs + (ty * 4 + i) * AP + d);
            #pragma unroll
            for (int j = 0; j < 4; j++) kv[j] = *(const float4*)(KP + (j * 16 + tx) * AP + d);
            #pragma unroll
            for (int i = 0; i < 4; i++)
                #pragma unroll
                for (int j = 0; j < 4; j++) {
                    s[i][j] = fmaf(qv[i].x, kv[j].x, s[i][j]);
                    s[i][j] = fmaf(qv[i].y, kv[j].y, s[i][j]);
                    s[i][j] = fmaf(qv[i].z, kv[j].z, s[i][j]);
                    s[i][j] = fmaf(qv[i].w, kv[j].w, s[i][j]);
                }
        }

        if (k0 == q0) {
            #pragma unroll
            for (int i = 0; i < 4; i++)
                #pragma unroll
                for (int j = 0; j < 4; j++)
                    if (j * 16 + tx > ty * 4 + i) s[i][j] = -1e30f;
        }

        #pragma unroll
        for (int i = 0; i < 4; i++) {
            float mx = fmaxf(fmaxf(s[i][0], s[i][1]), fmaxf(s[i][2], s[i][3]));
            #pragma unroll
            for (int o = 8; o > 0; o >>= 1) mx = fmaxf(mx, __shfl_xor_sync(0xffffffffu, mx, o));
            float mn = fmaxf(m_[i], mx);
            float corr = __expf(m_[i] - mn);
            float rs = 0.f;
            #pragma unroll
            for (int j = 0; j < 4; j++) { s[i][j] = __expf(s[i][j] - mn); rs += s[i][j]; }
            #pragma unroll
            for (int o = 8; o > 0; o >>= 1) rs += __shfl_xor_sync(0xffffffffu, rs, o);
            l_[i] = l_[i] * corr + rs;
            m_[i] = mn;
            #pragma unroll
            for (int j = 0; j < 4; j++) o_[i][j] *= corr;
        }

        __syncthreads();
        #pragma unroll
        for (int i = 0; i < 4; i++)
            #pragma unroll
            for (int j = 0; j < 4; j++)
                KP[(ty * 4 + i) * AP + j * 16 + tx] = s[i][j];
        __syncthreads();

        // O += P V : pv vectorized over k
        #pragma unroll 4
        for (int k = 0; k < 64; k += 4) {
            float4 pv[4];
            #pragma unroll
            for (int i = 0; i < 4; i++) pv[i] = *(const float4*)(KP + (ty * 4 + i) * AP + k);
            #pragma unroll
            for (int kk = 0; kk < 4; kk++) {
                float vv[4];
                #pragma unroll
                for (int j = 0; j < 4; j++) vv[j] = Vs[(k + kk) * AP + j * 16 + tx];
                #pragma unroll
                for (int i = 0; i < 4; i++) {
                    float p = (kk == 0) ? pv[i].x : (kk == 1) ? pv[i].y : (kk == 2) ? pv[i].z : pv[i].w;
                    #pragma unroll
                    for (int j = 0; j < 4; j++)
                        o_[i][j] = fmaf(p, vv[j], o_[i][j]);
                }
            }
        }
    }

    #pragma unroll
    for (int i = 0; i < 4; i++) {
        float inv = 1.f / l_[i];
        #pragma unroll
        for (int j = 0; j < 4; j++)
            out[(size_t)(b * TQ + q0 + ty * 4 + i) * DQ + h * HD + j * 16 + tx] = rtf32(o_[i][j] * inv);
    }
}

// ---------------- NLL / loss ----------------
__global__ void nll_kernel(const float* __restrict__ logits, const int* __restrict__ tgt,
                           float* __restrict__ nll) {
    int row = blockIdx.x;
    const float* lr = logits + (size_t)row * VQ;
    float m = -1e30f, s = 0.f;
    for (int j = threadIdx.x; j < VQ; j += 256) {
        float v = lr[j];
        if (v > m) { s = s * expf(m - v) + 1.f; m = v; }
        else       { s += expf(v - m); }
    }
    __shared__ float sm_[256], ssum[256];
    sm_[threadIdx.x] = m; ssum[threadIdx.x] = s; __syncthreads();
    for (int o = 128; o > 0; o >>= 1) {
        if (threadIdx.x < o) {
            float m2 = sm_[threadIdx.x + o], s2 = ssum[threadIdx.x + o];
            float M  = fmaxf(sm_[threadIdx.x], m2);
            ssum[threadIdx.x] = ssum[threadIdx.x] * expf(sm_[threadIdx.x] - M) + s2 * expf(m2 - M);
            sm_[threadIdx.x]  = M;
        }
        __syncthreads();
    }
    if (threadIdx.x == 0) {
        float lse = sm_[0] + logf(ssum[0]);
        int t = tgt[row];
        nll[row] = lse - lr[t];
    }
}

__global__ void loss_kernel(const float* __restrict__ nll, float* __restrict__ loss) {
    __shared__ float s[1024];
    float v = nll[threadIdx.x] + nll[threadIdx.x + 1024];
    s[threadIdx.x] = v; __syncthreads();
    for (int o = 512; o > 0; o >>= 1) {
        if (threadIdx.x < o) s[threadIdx.x] += s[threadIdx.x + o];
        __syncthreads();
    }
    if (threadIdx.x == 0) *loss = s[0] * (1.f / 2048.f);
}

// ---------------- launch ----------------
extern "C" void kernel_launch(void* const* d_in, const int* in_sizes, int n_in,
                              void* d_out, int out_size) {
    const int*   ids  = (const int*)d_in[0];
    const int*   tgt  = (const int*)d_in[1];
    const float* tok  = (const float*)d_in[2];
    const float* pos  = (const float*)d_in[3];
    const float* ln1w = (const float*)d_in[4];
    const float* ln1b = (const float*)d_in[5];
    const float* qkvw = (const float*)d_in[6];
    const float* qkvb = (const float*)d_in[7];
    const float* apw  = (const float*)d_in[8];
    const float* apb  = (const float*)d_in[9];
    const float* ln2w = (const float*)d_in[10];
    const float* ln2b = (const float*)d_in[11];
    const float* fcw  = (const float*)d_in[12];
    const float* fcb  = (const float*)d_in[13];
    const float* pw   = (const float*)d_in[14];
    const float* pb   = (const float*)d_in[15];
    const float* lnfw = (const float*)d_in[16];
    const float* lnfb = (const float*)d_in[17];

    float *x, *h, *qkv, *attn, *ffn, *nll, *lfb;
    float *wqkv, *wap, *wfc, *wpr, *tokt;
    cudaGetSymbolAddress((void**)&x,    g_x);
    cudaGetSymbolAddress((void**)&h,    g_h);
    cudaGetSymbolAddress((void**)&qkv,  g_qkv);
    cudaGetSymbolAddress((void**)&attn, g_attn);
    cudaGetSymbolAddress((void**)&ffn,  g_ffn);
    cudaGetSymbolAddress((void**)&nll,  g_nll);
    cudaGetSymbolAddress((void**)&lfb,  g_logits_fb);
    cudaGetSymbolAddress((void**)&wqkv, g_wqkv);
    cudaGetSymbolAddress((void**)&wap,  g_wap);
    cudaGetSymbolAddress((void**)&wfc,  g_wfc);
    cudaGetSymbolAddress((void**)&wpr,  g_wpr);
    cudaGetSymbolAddress((void**)&tokt, g_tokt);

    cudaFuncSetAttribute(flash_kernel, cudaFuncAttributeMaxDynamicSharedMemorySize, SMEM_ATT);
    cudaFuncSetAttribute(gemm_tf32<false,0>, cudaFuncAttributeMaxDynamicSharedMemorySize, SMEM_GEMM);
    cudaFuncSetAttribute(gemm_tf32<false,1>, cudaFuncAttributeMaxDynamicSharedMemorySize, SMEM_GEMM);
    cudaFuncSetAttribute(gemm_tf32<false,2>, cudaFuncAttributeMaxDynamicSharedMemorySize, SMEM_GEMM);
    cudaFuncSetAttribute(gemm_tf32<true,0>,  cudaFuncAttributeMaxDynamicSharedMemorySize, SMEM_GEMM);

    const long long LOGN = (long long)BT * VQ;
    float* out    = (float*)d_out;
    float* logits;
    float* lossp  = nullptr;
    if ((long long)out_size > LOGN) {
        lossp  = out;
        logits = out + ((long long)out_size - LOGN);
    } else if ((long long)out_size == LOGN) {
        logits = out;
    } else {
        lossp  = out;
        logits = lfb;
    }

    // pre-round weights to tf32 bit patterns (removes cvt from GEMM mainloop)
    {
        int n;
        n = LQ*DQ*3*DQ/4;  cvt_kernel<<<(n+255)/256, 256>>>((const float4*)qkvw, (float4*)wqkv, n);
        n = LQ*DQ*DQ/4;    cvt_kernel<<<(n+255)/256, 256>>>((const float4*)apw,  (float4*)wap,  n);
        n = LQ*DQ*4*DQ/4;  cvt_kernel<<<(n+255)/256, 256>>>((const float4*)fcw,  (float4*)wfc,  n);
        n = LQ*4*DQ*DQ/4;  cvt_kernel<<<(n+255)/256, 256>>>((const float4*)pw,   (float4*)wpr,  n);
        n = (int)((size_t)VQ*DQ/4); cvt_kernel<<<(n+255)/256, 256>>>((const float4*)tok, (float4*)tokt, n);
    }

    embed_kernel<<<(BT * DQ + 255) / 256, 256>>>(ids, tok, pos, x);

    for (int l = 0; l < LQ; l++) {
        ln_kernel<<<BT, 256>>>(x, ln1w + l * DQ, ln1b + l * DQ, h);
        gemm_tf32<false, 0><<<dim3((3 * DQ) / 128, BT / 128), 256, SMEM_GEMM>>>(
            h, wqkv + (size_t)l * DQ * 3 * DQ, qkvb + l * 3 * DQ, nullptr, qkv, BT, 3 * DQ, DQ);
        flash_kernel<<<dim3(TQ / 64, HQ, BQ), 256, SMEM_ATT>>>(qkv, attn);
        gemm_tf32<false, 1><<<dim3(DQ / 128, BT / 128), 256, SMEM_GEMM>>>(
            attn, wap + (size_t)l * DQ * DQ, apb + l * DQ, x, x, BT, DQ, DQ);
        ln_kernel<<<BT, 256>>>(x, ln2w + l * DQ, ln2b + l * DQ, h);
        gemm_tf32<false, 2><<<dim3((4 * DQ) / 128, BT / 128), 256, SMEM_GEMM>>>(
            h, wfc + (size_t)l * DQ * 4 * DQ, fcb + l * 4 * DQ, nullptr, ffn, BT, 4 * DQ, DQ);
        gemm_tf32<false, 1><<<dim3(DQ / 128, BT / 128), 256, SMEM_GEMM>>>(
            ffn, wpr + (size_t)l * 4 * DQ * DQ, pb + l * DQ, x, x, BT, DQ, 4 * DQ);
    }

    ln_kernel<<<BT, 256>>>(x, lnfw, lnfb, h);
    gemm_tf32<true, 0><<<dim3(BT / 128, (VQ + 127) / 128), 256, SMEM_GEMM>>>(
        h, tokt, nullptr, nullptr, logits, BT, VQ, DQ);

    if (lossp) {
        nll_kernel<<<BT, 256>>>(logits, tgt, nll);
        loss_kernel<<<1, 1024>>>(nll, lossp);
    }
}

// round 5
// speedup vs baseline: 5.6807x; 1.0928x over previous
#include <cuda_runtime.h>
#include <math.h>
#include <stdint.h>

// ---------------- problem constants ----------------
#define BQ 2
#define TQ 1024
#define DQ 768
#define LQ 4
#define HQ 12
#define VQ 50257
#define BT (BQ*TQ)
#define HD 64
#define NT_LM 393   // ceil(VQ/128)

// ---------------- scratch ----------------
__device__ float g_x   [BT*DQ];
__device__ float g_h   [BT*DQ];
__device__ float g_qkv [BT*3*DQ];
__device__ float g_attn[BT*DQ];
__device__ float g_ffn [BT*4*DQ];
__device__ float g_nll [BT];
__device__ float g_pm  [BT*NT_LM];
__device__ float g_ps  [BT*NT_LM];
__device__ float g_logits_fb[102926336];
// tf32-rounded weight copies
__device__ float g_wqkv[LQ*DQ*3*DQ];
__device__ float g_wap [LQ*DQ*DQ];
__device__ float g_wfc [LQ*DQ*4*DQ];
__device__ float g_wpr [LQ*4*DQ*DQ];
__device__ float g_tokt[(size_t)VQ*DQ];

__device__ __forceinline__ uint32_t f2tf32(float x) {
    uint32_t u; asm("cvt.rna.tf32.f32 %0, %1;" : "=r"(u) : "f"(x)); return u;
}
__device__ __forceinline__ float rtf32(float x) { return __uint_as_float(f2tf32(x)); }
__device__ __forceinline__ void lse_merge(float& m, float& s, float m2, float s2) {
    float M = fmaxf(m, m2);
    s = s * __expf(m - M) + s2 * __expf(m2 - M);
    m = M;
}

// ---------------- tf32 pre-round ----------------
__global__ void cvt_kernel(const float4* __restrict__ src, float4* __restrict__ dst, int n4) {
    int i = blockIdx.x * 256 + threadIdx.x;
    if (i >= n4) return;
    float4 v = src[i];
    v.x = rtf32(v.x); v.y = rtf32(v.y); v.z = rtf32(v.z); v.w = rtf32(v.w);
    dst[i] = v;
}

// ---------------- embedding ----------------
__global__ void embed_kernel(const int* __restrict__ ids,
                             const float* __restrict__ tok,
                             const float* __restrict__ pos,
                             float* __restrict__ x) {
    int i = blockIdx.x * 256 + threadIdx.x;
    if (i >= BT * DQ) return;
    int r = i / DQ, d = i - r * DQ;
    int id = ids[r];
    x[i] = tok[(size_t)id * DQ + d] + pos[(r % TQ) * DQ + d];
}

// ---------------- layernorm (rounds output to tf32) ----------------
__global__ void ln_kernel(const float* __restrict__ x,
                          const float* __restrict__ w,
                          const float* __restrict__ b,
                          float* __restrict__ y) {
    int row = blockIdx.x;
    const float* xr = x + (size_t)row * DQ;
    float s = 0.f, q = 0.f;
    for (int i = threadIdx.x; i < DQ; i += 256) { float v = xr[i]; s += v; q += v * v; }
    __shared__ float ss[256], sq[256];
    ss[threadIdx.x] = s; sq[threadIdx.x] = q; __syncthreads();
    for (int o = 128; o > 0; o >>= 1) {
        if (threadIdx.x < o) { ss[threadIdx.x] += ss[threadIdx.x + o]; sq[threadIdx.x] += sq[threadIdx.x + o]; }
        __syncthreads();
    }
    float mean = ss[0] * (1.f / DQ);
    float var  = sq[0] * (1.f / DQ) - mean * mean;
    float inv  = rsqrtf(var + 1e-5f);
    float* yr = y + (size_t)row * DQ;
    for (int i = threadIdx.x; i < DQ; i += 256)
        yr[i] = rtf32((xr[i] - mean) * inv * w[i] + b[i]);
}

// ---------------- common mma / cp.async helpers ----------------
__device__ __forceinline__ void mma8(float* c, const uint32_t* a, const uint32_t* b) {
    asm volatile("mma.sync.aligned.m16n8k8.row.col.f32.tf32.tf32.f32 "
                 "{%0,%1,%2,%3}, {%4,%5,%6,%7}, {%8,%9}, {%0,%1,%2,%3};\n"
                 : "+f"(c[0]), "+f"(c[1]), "+f"(c[2]), "+f"(c[3])
                 : "r"(a[0]), "r"(a[1]), "r"(a[2]), "r"(a[3]), "r"(b[0]), "r"(b[1]));
}
__device__ __forceinline__ void cpa16(uint32_t dst, const void* src) {
    asm volatile("cp.async.cg.shared.global [%0], [%1], 16;\n" :: "r"(dst), "l"(src));
}
__device__ __forceinline__ void cpa16z(uint32_t dst, const void* src, int bytes) {
    asm volatile("cp.async.cg.shared.global [%0], [%1], 16, %2;\n" :: "r"(dst), "l"(src), "r"(bytes));
}

#define GA_STRIDE 36
#define GB_STRIDE 136
#define NSTAGE 3
#define SMEM_A_FLOATS (NSTAGE*128*GA_STRIDE)
#define SMEM_GEMM ((SMEM_A_FLOATS + NSTAGE*128*GA_STRIDE) * 4)

// ---------------- layer GEMMs (no trans) ----------------
template<int EPI>   // 0 bias+round(tf32), 1 bias+res, 2 bias+gelu+round
__global__ __launch_bounds__(256)
void gemm_tf32(const float* __restrict__ A, const float* __restrict__ B,
               const float* __restrict__ bias, const float* __restrict__ res,
               float* __restrict__ C, int M, int N, int K) {
    extern __shared__ float sm[];
    float* As = sm;
    float* Bs = sm + SMEM_A_FLOATS;

    const int tid  = threadIdx.x;
    const int lane = tid & 31, wid = tid >> 5;
    const int wm = (wid & 1) * 64, wn = (wid >> 1) * 32;
    const int g = lane >> 2, tq = lane & 3;
    const int m0 = blockIdx.y * 128, n0 = blockIdx.x * 128;

    const uint32_t sA = (uint32_t)__cvta_generic_to_shared(As);
    const uint32_t sB = (uint32_t)__cvta_generic_to_shared(Bs);

    const int arow = tid >> 3, acol = (tid & 7) << 2;
    const int bk = tid >> 5, bn = (tid & 31) << 2;

    auto load_tile = [&](int t) {
        int k0 = t * 32, st = t % NSTAGE;
        #pragma unroll
        for (int it = 0; it < 4; it++) {
            int r = arow + it * 32;
            cpa16(sA + ((st * 128 + r) * GA_STRIDE + acol) * 4,
                  A + (size_t)(m0 + r) * K + k0 + acol);
        }
        #pragma unroll
        for (int it = 0; it < 4; it++) {
            int r = bk + it * 8;
            cpa16(sB + ((st * 32 + r) * GB_STRIDE + bn) * 4,
                  B + (size_t)(k0 + r) * N + n0 + bn);
        }
    };

    float acc[4][4][4] = {};
    const int nt = K / 32;

    load_tile(0);
    asm volatile("cp.async.commit_group;\n");
    load_tile(1);
    asm volatile("cp.async.commit_group;\n");

    for (int t = 0; t < nt; t++) {
        if (t + 2 < nt) load_tile(t + 2);
        asm volatile("cp.async.commit_group;\n");
        asm volatile("cp.async.wait_group 2;\n");
        __syncthreads();

        const int st = t % NSTAGE;
        const float* Ab = As + st * 128 * GA_STRIDE;
        const float* Bb = Bs + st * 32 * GB_STRIDE;
        #pragma unroll
        for (int ks = 0; ks < 4; ks++) {
            int k = ks * 8 + tq;
            uint32_t af[4][4], bf[4][2];
            #pragma unroll
            for (int mi = 0; mi < 4; mi++) {
                int m = wm + mi * 16 + g;
                af[mi][0] = __float_as_uint(Ab[m * GA_STRIDE + k]);
                af[mi][1] = __float_as_uint(Ab[(m + 8) * GA_STRIDE + k]);
                af[mi][2] = __float_as_uint(Ab[m * GA_STRIDE + k + 4]);
                af[mi][3] = __float_as_uint(Ab[(m + 8) * GA_STRIDE + k + 4]);
            }
            #pragma unroll
            for (int ni = 0; ni < 4; ni++) {
                int n = wn + ni * 8 + g;
                bf[ni][0] = __float_as_uint(Bb[k * GB_STRIDE + n]);
                bf[ni][1] = __float_as_uint(Bb[(k + 4) * GB_STRIDE + n]);
            }
            #pragma unroll
            for (int mi = 0; mi < 4; mi++)
                #pragma unroll
                for (int ni = 0; ni < 4; ni++)
                    mma8(acc[mi][ni], af[mi], bf[ni]);
        }
        __syncthreads();
    }

    #pragma unroll
    for (int mi = 0; mi < 4; mi++) {
        #pragma unroll
        for (int ni = 0; ni < 4; ni++) {
            int m = m0 + wm + mi * 16 + g;
            int n = n0 + wn + ni * 8 + tq * 2;
            #pragma unroll
            for (int half = 0; half < 2; half++) {
                int mm = m + half * 8;
                #pragma unroll
                for (int e = 0; e < 2; e++) {
                    int nn = n + e;
                    float v = acc[mi][ni][half * 2 + e] + bias[nn];
                    if (EPI == 0) v = rtf32(v);
                    if (EPI == 1) v += res[(size_t)mm * N + nn];
                    if (EPI == 2) {
                        v = 0.5f * v * (1.f + erff(v * 0.70710678118654752440f));
                        v = rtf32(v);
                    }
                    C[(size_t)mm * N + nn] = v;
                }
            }
        }
    }
}

// ---------------- LM-head GEMM (B transposed) + fused NLL partials ----------------
__global__ __launch_bounds__(256)
void gemm_lm(const float* __restrict__ A, const float* __restrict__ B,
             float* __restrict__ C, float* __restrict__ pm, float* __restrict__ ps,
             int M, int N, int K) {
    extern __shared__ float sm[];
    float* As = sm;
    float* Bs = sm + SMEM_A_FLOATS;

    const int tid  = threadIdx.x;
    const int lane = tid & 31, wid = tid >> 5;
    const int wm = (wid & 1) * 64, wn = (wid >> 1) * 32;
    const int g = lane >> 2, tq = lane & 3;
    const int m0 = blockIdx.x * 128, n0 = blockIdx.y * 128;
    const int tileY = blockIdx.y, NTt = gridDim.y;

    const uint32_t sA = (uint32_t)__cvta_generic_to_shared(As);
    const uint32_t sB = (uint32_t)__cvta_generic_to_shared(Bs);

    const int arow = tid >> 3, acol = (tid & 7) << 2;

    auto load_tile = [&](int t) {
        int k0 = t * 32, st = t % NSTAGE;
        #pragma unroll
        for (int it = 0; it < 4; it++) {
            int r = arow + it * 32;
            cpa16(sA + ((st * 128 + r) * GA_STRIDE + acol) * 4,
                  A + (size_t)(m0 + r) * K + k0 + acol);
        }
        #pragma unroll
        for (int it = 0; it < 4; it++) {
            int r = arow + it * 32;
            int n = n0 + r;
            int ok = (n < N);
            cpa16z(sB + ((st * 128 + r) * GA_STRIDE + acol) * 4,
                   B + (size_t)(ok ? n : (N - 1)) * K + k0 + acol, ok ? 16 : 0);
        }
    };

    float acc[4][4][4] = {};
    const int nt = K / 32;

    load_tile(0);
    asm volatile("cp.async.commit_group;\n");
    load_tile(1);
    asm volatile("cp.async.commit_group;\n");

    for (int t = 0; t < nt; t++) {
        if (t + 2 < nt) load_tile(t + 2);
        asm volatile("cp.async.commit_group;\n");
        asm volatile("cp.async.wait_group 2;\n");
        __syncthreads();

        const int st = t % NSTAGE;
        const float* Ab = As + st * 128 * GA_STRIDE;
        const float* Bb = Bs + st * 128 * GA_STRIDE;
        #pragma unroll
        for (int ks = 0; ks < 4; ks++) {
            int k = ks * 8 + tq;
            uint32_t af[4][4], bf[4][2];
            #pragma unroll
            for (int mi = 0; mi < 4; mi++) {
                int m = wm + mi * 16 + g;
                af[mi][0] = __float_as_uint(Ab[m * GA_STRIDE + k]);
                af[mi][1] = __float_as_uint(Ab[(m + 8) * GA_STRIDE + k]);
                af[mi][2] = __float_as_uint(Ab[m * GA_STRIDE + k + 4]);
                af[mi][3] = __float_as_uint(Ab[(m + 8) * GA_STRIDE + k + 4]);
            }
            #pragma unroll
            for (int ni = 0; ni < 4; ni++) {
                int n = wn + ni * 8 + g;
                bf[ni][0] = __float_as_uint(Bb[n * GA_STRIDE + k]);
                bf[ni][1] = __float_as_uint(Bb[n * GA_STRIDE + k + 4]);
            }
            #pragma unroll
            for (int mi = 0; mi < 4; mi++)
                #pragma unroll
                for (int ni = 0; ni < 4; ni++)
                    mma8(acc[mi][ni], af[mi], bf[ni]);
        }
        __syncthreads();
    }

    // write logits
    #pragma unroll
    for (int mi = 0; mi < 4; mi++) {
        #pragma unroll
        for (int ni = 0; ni < 4; ni++) {
            int m = m0 + wm + mi * 16 + g;
            int n = n0 + wn + ni * 8 + tq * 2;
            #pragma unroll
            for (int half = 0; half < 2; half++) {
                int mm = m + half * 8;
                #pragma unroll
                for (int e = 0; e < 2; e++) {
                    int nn = n + e;
                    if (nn >= N) continue;
                    C[(size_t)mm * N + nn] = acc[mi][ni][half * 2 + e];
                }
            }
        }
    }

    // fused per-tile logsumexp partials
    float* sPm = sm;            // reuse dynamic smem (mainloop done)
    float* sPs = sm + 512;
    #pragma unroll
    for (int mi = 0; mi < 4; mi++) {
        #pragma unroll
        for (int half = 0; half < 2; half++) {
            float lm = -1e30f, lsum = 0.f;
            #pragma unroll
            for (int ni = 0; ni < 4; ni++) {
                #pragma unroll
                for (int e = 0; e < 2; e++) {
                    int nn = n0 + wn + ni * 8 + tq * 2 + e;
                    if (nn < N) lm = fmaxf(lm, acc[mi][ni][half * 2 + e]);
                }
            }
            #pragma unroll
            for (int ni = 0; ni < 4; ni++) {
                #pragma unroll
                for (int e = 0; e < 2; e++) {
                    int nn = n0 + wn + ni * 8 + tq * 2 + e;
                    if (nn < N) lsum += __expf(acc[mi][ni][half * 2 + e] - lm);
                }
            }
            #pragma unroll
            for (int o = 1; o <= 2; o <<= 1) {
                float m2 = __shfl_xor_sync(0xffffffffu, lm, o);
                float s2 = __shfl_xor_sync(0xffffffffu, lsum, o);
                lse_merge(lm, lsum, m2, s2);
            }
            if (tq == 0) {
                int rl = wm + mi * 16 + half * 8 + g;
                sPm[rl * 4 + (wid >> 1)] = lm;
                sPs[rl * 4 + (wid >> 1)] = lsum;
            }
        }
    }
    __syncthreads();
    if (tid < 128) {
        float M_ = sPm[tid * 4], S_ = sPs[tid * 4];
        #pragma unroll
        for (int gi = 1; gi < 4; gi++) lse_merge(M_, S_, sPm[tid * 4 + gi], sPs[tid * 4 + gi]);
        pm[(size_t)(m0 + tid) * NTt + tileY] = M_;
        ps[(size_t)(m0 + tid) * NTt + tileY] = S_;
    }
}

// ---------------- flash attention (tf32 tensor cores) ----------------
#define FQS 68
#define FVS 72
#define SMEM_FL ((64*FQS*2 + 64*FVS)*4)   // 53248
__global__ __launch_bounds__(128)
void flash_mma(const float* __restrict__ qkv, float* __restrict__ out) {
    extern __shared__ float sm[];
    float* Qs = sm;
    float* Ks = sm + 64 * FQS;          // K tile, reused for P
    float* Vs = sm + 2 * 64 * FQS;

    const int tid = threadIdx.x;
    const int lane = tid & 31, wid = tid >> 5;
    const int g = lane >> 2, tq = lane & 3;
    const int q0 = blockIdx.x * 64;
    const int h = blockIdx.y, b = blockIdx.z;
    const int r0 = wid * 16 + g;        // warp-local row (and r0+8)

    // load Q (scaled)
    #pragma unroll
    for (int i = 0; i < 8; i++) {
        int idx = tid + i * 128;
        int r = idx >> 4, d0 = (idx & 15) << 2;
        float4 v = *(const float4*)(qkv + (size_t)(b * TQ + q0 + r) * (3 * DQ) + h * HD + d0);
        v.x *= 0.125f; v.y *= 0.125f; v.z *= 0.125f; v.w *= 0.125f;
        *(float4*)(Qs + r * FQS + d0) = v;
    }

    float m0r = -1e30f, m1r = -1e30f, l0 = 0.f, l1 = 0.f;
    float oc[8][4] = {};

    const int ktiles = q0 / 64 + 1;
    for (int kt = 0; kt < ktiles; kt++) {
        int k0 = kt * 64;
        __syncthreads();
        #pragma unroll
        for (int i = 0; i < 8; i++) {
            int idx = tid + i * 128;
            int r = idx >> 4, d0 = (idx & 15) << 2;
            const float* src = qkv + (size_t)(b * TQ + k0 + r) * (3 * DQ) + h * HD + d0;
            *(float4*)(Ks + r * FQS + d0) = *(const float4*)(src + DQ);
            *(float4*)(Vs + r * FVS + d0) = *(const float4*)(src + 2 * DQ);
        }
        __syncthreads();

        // S = Q K^T  (warp: 16 rows x 64 cols)
        float sc[8][4] = {};
        #pragma unroll
        for (int kk = 0; kk < 8; kk++) {
            uint32_t a[4];
            a[0] = __float_as_uint(Qs[r0 * FQS + kk * 8 + tq]);
            a[1] = __float_as_uint(Qs[(r0 + 8) * FQS + kk * 8 + tq]);
            a[2] = __float_as_uint(Qs[r0 * FQS + kk * 8 + tq + 4]);
            a[3] = __float_as_uint(Qs[(r0 + 8) * FQS + kk * 8 + tq + 4]);
            #pragma unroll
            for (int ni = 0; ni < 8; ni++) {
                uint32_t bb[2];
                bb[0] = __float_as_uint(Ks[(ni * 8 + g) * FQS + kk * 8 + tq]);
                bb[1] = __float_as_uint(Ks[(ni * 8 + g) * FQS + kk * 8 + tq + 4]);
                mma8(sc[ni], a, bb);
            }
        }

        if (k0 == q0) {   // causal mask on diagonal tile
            #pragma unroll
            for (int ni = 0; ni < 8; ni++) {
                int c0 = ni * 8 + 2 * tq, c1 = c0 + 1;
                if (c0 > r0) sc[ni][0] = -1e30f;
                if (c1 > r0) sc[ni][1] = -1e30f;
                if (c0 > r0 + 8) sc[ni][2] = -1e30f;
                if (c1 > r0 + 8) sc[ni][3] = -1e30f;
            }
        }

        // online softmax (rows r0 / r0+8)
        float mx0 = -1e30f, mx1 = -1e30f;
        #pragma unroll
        for (int ni = 0; ni < 8; ni++) {
            mx0 = fmaxf(mx0, fmaxf(sc[ni][0], sc[ni][1]));
            mx1 = fmaxf(mx1, fmaxf(sc[ni][2], sc[ni][3]));
        }
        #pragma unroll
        for (int o = 1; o <= 2; o <<= 1) {
            mx0 = fmaxf(mx0, __shfl_xor_sync(0xffffffffu, mx0, o));
            mx1 = fmaxf(mx1, __shfl_xor_sync(0xffffffffu, mx1, o));
        }
        float nm0 = fmaxf(m0r, mx0), nm1 = fmaxf(m1r, mx1);
        float cr0 = __expf(m0r - nm0), cr1 = __expf(m1r - nm1);
        float rs0 = 0.f, rs1 = 0.f;
        #pragma unroll
        for (int ni = 0; ni < 8; ni++) {
            sc[ni][0] = __expf(sc[ni][0] - nm0); rs0 += sc[ni][0];
            sc[ni][1] = __expf(sc[ni][1] - nm0); rs0 += sc[ni][1];
            sc[ni][2] = __expf(sc[ni][2] - nm1); rs1 += sc[ni][2];
            sc[ni][3] = __expf(sc[ni][3] - nm1); rs1 += sc[ni][3];
        }
        #pragma unroll
        for (int o = 1; o <= 2; o <<= 1) {
            rs0 += __shfl_xor_sync(0xffffffffu, rs0, o);
            rs1 += __shfl_xor_sync(0xffffffffu, rs1, o);
        }
        l0 = l0 * cr0 + rs0; l1 = l1 * cr1 + rs1;
        m0r = nm0; m1r = nm1;
        #pragma unroll
        for (int ni = 0; ni < 8; ni++) {
            oc[ni][0] *= cr0; oc[ni][1] *= cr0;
            oc[ni][2] *= cr1; oc[ni][3] *= cr1;
        }

        __syncthreads();   // all warps done reading K
        #pragma unroll
        for (int ni = 0; ni < 8; ni++) {
            Ks[r0 * FQS + ni * 8 + 2 * tq]           = rtf32(sc[ni][0]);
            Ks[r0 * FQS + ni * 8 + 2 * tq + 1]       = rtf32(sc[ni][1]);
            Ks[(r0 + 8) * FQS + ni * 8 + 2 * tq]     = rtf32(sc[ni][2]);
            Ks[(r0 + 8) * FQS + ni * 8 + 2 * tq + 1] = rtf32(sc[ni][3]);
        }
        __syncthreads();

        // O += P V
        #pragma unroll
        for (int kk = 0; kk < 8; kk++) {
            uint32_t a[4];
            a[0] = __float_as_uint(Ks[r0 * FQS + kk * 8 + tq]);
            a[1] = __float_as_uint(Ks[(r0 + 8) * FQS + kk * 8 + tq]);
            a[2] = __float_as_uint(Ks[r0 * FQS + kk * 8 + tq + 4]);
            a[3] = __float_as_uint(Ks[(r0 + 8) * FQS + kk * 8 + tq + 4]);
            #pragma unroll
            for (int ni = 0; ni < 8; ni++) {
                uint32_t bb[2];
                bb[0] = __float_as_uint(Vs[(kk * 8 + tq) * FVS + ni * 8 + g]);
                bb[1] = __float_as_uint(Vs[(kk * 8 + tq + 4) * FVS + ni * 8 + g]);
                mma8(oc[ni], a, bb);
            }
        }
    }

    float i0 = 1.f / l0, i1 = 1.f / l1;
    float* o0 = out + (size_t)(b * TQ + q0 + r0) * DQ + h * HD;
    float* o1 = out + (size_t)(b * TQ + q0 + r0 + 8) * DQ + h * HD;
    #pragma unroll
    for (int ni = 0; ni < 8; ni++) {
        o0[ni * 8 + 2 * tq]     = rtf32(oc[ni][0] * i0);
        o0[ni * 8 + 2 * tq + 1] = rtf32(oc[ni][1] * i0);
        o1[ni * 8 + 2 * tq]     = rtf32(oc[ni][2] * i1);
        o1[ni * 8 + 2 * tq + 1] = rtf32(oc[ni][3] * i1);
    }
}

// ---------------- NLL reduce (over LM-tile partials) + loss ----------------
__global__ void nll_reduce(const float* __restrict__ pm, const float* __restrict__ ps,
                           const float* __restrict__ logits, const int* __restrict__ tgt,
                           float* __restrict__ nll) {
    int row = blockIdx.x, t = threadIdx.x;
    float M = -1e30f, S = 0.f;
    for (int j = t; j < NT_LM; j += 128)
        lse_merge(M, S, pm[(size_t)row * NT_LM + j], ps[(size_t)row * NT_LM + j]);
    __shared__ float sm_[128], ss_[128];
    sm_[t] = M; ss_[t] = S; __syncthreads();
    for (int o = 64; o > 0; o >>= 1) {
        if (t < o) {
            float m2 = sm_[t + o], s2 = ss_[t + o];
            float mm = sm_[t], ssv = ss_[t];
            lse_merge(mm, ssv, m2, s2);
            sm_[t] = mm; ss_[t] = ssv;
        }
        __syncthreads();
    }
    if (t == 0) {
        float lse = sm_[0] + logf(ss_[0]);
        nll[row] = lse - logits[(size_t)row * VQ + tgt[row]];
    }
}

__global__ void loss_kernel(const float* __restrict__ nll, float* __restrict__ loss) {
    __shared__ float s[1024];
    float v = nll[threadIdx.x] + nll[threadIdx.x + 1024];
    s[threadIdx.x] = v; __syncthreads();
    for (int o = 512; o > 0; o >>= 1) {
        if (threadIdx.x < o) s[threadIdx.x] += s[threadIdx.x + o];
        __syncthreads();
    }
    if (threadIdx.x == 0) *loss = s[0] * (1.f / 2048.f);
}

// ---------------- launch ----------------
extern "C" void kernel_launch(void* const* d_in, const int* in_sizes, int n_in,
                              void* d_out, int out_size) {
    const int*   ids  = (const int*)d_in[0];
    const int*   tgt  = (const int*)d_in[1];
    const float* tok  = (const float*)d_in[2];
    const float* pos  = (const float*)d_in[3];
    const float* ln1w = (const float*)d_in[4];
    const float* ln1b = (const float*)d_in[5];
    const float* qkvw = (const float*)d_in[6];
    const float* qkvb = (const float*)d_in[7];
    const float* apw  = (const float*)d_in[8];
    const float* apb  = (const float*)d_in[9];
    const float* ln2w = (const float*)d_in[10];
    const float* ln2b = (const float*)d_in[11];
    const float* fcw  = (const float*)d_in[12];
    const float* fcb  = (const float*)d_in[13];
    const float* pw   = (const float*)d_in[14];
    const float* pb   = (const float*)d_in[15];
    const float* lnfw = (const float*)d_in[16];
    const float* lnfb = (const float*)d_in[17];

    float *x, *h, *qkv, *attn, *ffn, *nll, *lfb, *pm, *ps;
    float *wqkv, *wap, *wfc, *wpr, *tokt;
    cudaGetSymbolAddress((void**)&x,    g_x);
    cudaGetSymbolAddress((void**)&h,    g_h);
    cudaGetSymbolAddress((void**)&qkv,  g_qkv);
    cudaGetSymbolAddress((void**)&attn, g_attn);
    cudaGetSymbolAddress((void**)&ffn,  g_ffn);
    cudaGetSymbolAddress((void**)&nll,  g_nll);
    cudaGetSymbolAddress((void**)&lfb,  g_logits_fb);
    cudaGetSymbolAddress((void**)&pm,   g_pm);
    cudaGetSymbolAddress((void**)&ps,   g_ps);
    cudaGetSymbolAddress((void**)&wqkv, g_wqkv);
    cudaGetSymbolAddress((void**)&wap,  g_wap);
    cudaGetSymbolAddress((void**)&wfc,  g_wfc);
    cudaGetSymbolAddress((void**)&wpr,  g_wpr);
    cudaGetSymbolAddress((void**)&tokt, g_tokt);

    cudaFuncSetAttribute(flash_mma, cudaFuncAttributeMaxDynamicSharedMemorySize, SMEM_FL);
    cudaFuncSetAttribute(gemm_tf32<0>, cudaFuncAttributeMaxDynamicSharedMemorySize, SMEM_GEMM);
    cudaFuncSetAttribute(gemm_tf32<1>, cudaFuncAttributeMaxDynamicSharedMemorySize, SMEM_GEMM);
    cudaFuncSetAttribute(gemm_tf32<2>, cudaFuncAttributeMaxDynamicSharedMemorySize, SMEM_GEMM);
    cudaFuncSetAttribute(gemm_lm,      cudaFuncAttributeMaxDynamicSharedMemorySize, SMEM_GEMM);

    const long long LOGN = (long long)BT * VQ;
    float* out    = (float*)d_out;
    float* logits;
    float* lossp  = nullptr;
    if ((long long)out_size > LOGN) {
        lossp  = out;
        logits = out + ((long long)out_size - LOGN);
    } else if ((long long)out_size == LOGN) {
        logits = out;
    } else {
        lossp  = out;
        logits = lfb;
    }

    {   // pre-round weights to tf32
        int n;
        n = LQ*DQ*3*DQ/4;  cvt_kernel<<<(n+255)/256, 256>>>((const float4*)qkvw, (float4*)wqkv, n);
        n = LQ*DQ*DQ/4;    cvt_kernel<<<(n+255)/256, 256>>>((const float4*)apw,  (float4*)wap,  n);
        n = LQ*DQ*4*DQ/4;  cvt_kernel<<<(n+255)/256, 256>>>((const float4*)fcw,  (float4*)wfc,  n);
        n = LQ*4*DQ*DQ/4;  cvt_kernel<<<(n+255)/256, 256>>>((const float4*)pw,   (float4*)wpr,  n);
        n = (int)((size_t)VQ*DQ/4); cvt_kernel<<<(n+255)/256, 256>>>((const float4*)tok, (float4*)tokt, n);
    }

    embed_kernel<<<(BT * DQ + 255) / 256, 256>>>(ids, tok, pos, x);

    for (int l = 0; l < LQ; l++) {
        ln_kernel<<<BT, 256>>>(x, ln1w + l * DQ, ln1b + l * DQ, h);
        gemm_tf32<0><<<dim3((3 * DQ) / 128, BT / 128), 256, SMEM_GEMM>>>(
            h, wqkv + (size_t)l * DQ * 3 * DQ, qkvb + l * 3 * DQ, nullptr, qkv, BT, 3 * DQ, DQ);
        flash_mma<<<dim3(TQ / 64, HQ, BQ), 128, SMEM_FL>>>(qkv, attn);
        gemm_tf32<1><<<dim3(DQ / 128, BT / 128), 256, SMEM_GEMM>>>(
            attn, wap + (size_t)l * DQ * DQ, apb + l * DQ, x, x, BT, DQ, DQ);
        ln_kernel<<<BT, 256>>>(x, ln2w + l * DQ, ln2b + l * DQ, h);
        gemm_tf32<2><<<dim3((4 * DQ) / 128, BT / 128), 256, SMEM_GEMM>>>(
            h, wfc + (size_t)l * DQ * 4 * DQ, fcb + l * 4 * DQ, nullptr, ffn, BT, 4 * DQ, DQ);
        gemm_tf32<1><<<dim3(DQ / 128, BT / 128), 256, SMEM_GEMM>>>(
            ffn, wpr + (size_t)l * 4 * DQ * DQ, pb + l * DQ, x, x, BT, DQ, 4 * DQ);
    }

    ln_kernel<<<BT, 256>>>(x, lnfw, lnfb, h);
    gemm_lm<<<dim3(BT / 128, NT_LM), 256, SMEM_GEMM>>>(
        h, tokt, logits, pm, ps, BT, VQ, DQ);

    if (lossp) {
        nll_reduce<<<BT, 128>>>(pm, ps, logits, tgt, nll);
        loss_kernel<<<1, 1024>>>(nll, lossp);
    }
}

// round 6
// speedup vs baseline: 5.8200x; 1.0245x over previous
#include <cuda_runtime.h>
#include <math.h>
#include <stdint.h>

// ---------------- problem constants ----------------
#define BQ 2
#define TQ 1024
#define DQ 768
#define LQ 4
#define HQ 12
#define VQ 50257
#define BT (BQ*TQ)
#define HD 64
#define NT_LM 393   // ceil(VQ/128)

// ---------------- scratch ----------------
__device__ float g_x   [BT*DQ];
__device__ float g_h   [BT*DQ];
__device__ float g_qkv [BT*3*DQ];
__device__ float g_attn[BT*DQ];
__device__ float g_ffn [BT*4*DQ];
__device__ float g_nll [BT];
__device__ float g_pm  [BT*NT_LM];
__device__ float g_ps  [BT*NT_LM];
__device__ float g_logits_fb[102926336];
// tf32-rounded, TRANSPOSED ([N][K]) weight copies
__device__ float g_wqkv[LQ*DQ*3*DQ];
__device__ float g_wap [LQ*DQ*DQ];
__device__ float g_wfc [LQ*DQ*4*DQ];
__device__ float g_wpr [LQ*4*DQ*DQ];
__device__ float g_tokt[(size_t)VQ*DQ];   // rounded only (already [V][K])

__device__ __forceinline__ uint32_t f2tf32(float x) {
    uint32_t u; asm("cvt.rna.tf32.f32 %0, %1;" : "=r"(u) : "f"(x)); return u;
}
__device__ __forceinline__ float rtf32(float x) { return __uint_as_float(f2tf32(x)); }
__device__ __forceinline__ void lse_merge(float& m, float& s, float m2, float s2) {
    float M = fmaxf(m, m2);
    s = s * __expf(m - M) + s2 * __expf(m2 - M);
    m = M;
}

// ---------------- tf32 round (tok_emb) ----------------
__global__ void cvt_kernel(const float4* __restrict__ src, float4* __restrict__ dst, int n4) {
    int i = blockIdx.x * 256 + threadIdx.x;
    if (i >= n4) return;
    float4 v = src[i];
    v.x = rtf32(v.x); v.y = rtf32(v.y); v.z = rtf32(v.z); v.w = rtf32(v.w);
    dst[i] = v;
}

// ---------------- tf32 round + transpose: [L][K][N] -> [L][N][K] ----------------
__global__ __launch_bounds__(256)
void cvtT_kernel(const float* __restrict__ src, float* __restrict__ dst, int K, int N) {
    __shared__ float t[32][33];
    int l = blockIdx.z;
    int k0 = blockIdx.x * 32, n0 = blockIdx.y * 32;
    const float* S = src + (size_t)l * K * N;
    float* D = dst + (size_t)l * K * N;
    int tid = threadIdx.x;
    int r = tid >> 3, c4 = (tid & 7) << 2;
    float4 v = *(const float4*)(S + (size_t)(k0 + r) * N + n0 + c4);
    t[r][c4 + 0] = rtf32(v.x); t[r][c4 + 1] = rtf32(v.y);
    t[r][c4 + 2] = rtf32(v.z); t[r][c4 + 3] = rtf32(v.w);
    __syncthreads();
    float4 o;
    o.x = t[c4 + 0][r]; o.y = t[c4 + 1][r]; o.z = t[c4 + 2][r]; o.w = t[c4 + 3][r];
    *(float4*)(D + (size_t)(n0 + r) * K + k0 + c4) = o;
}

// ---------------- embedding ----------------
__global__ void embed_kernel(const int* __restrict__ ids,
                             const float* __restrict__ tok,
                             const float* __restrict__ pos,
                             float* __restrict__ x) {
    int i = blockIdx.x * 256 + threadIdx.x;
    if (i >= BT * DQ) return;
    int r = i / DQ, d = i - r * DQ;
    int id = ids[r];
    x[i] = tok[(size_t)id * DQ + d] + pos[(r % TQ) * DQ + d];
}

// ---------------- layernorm (rounds output to tf32) ----------------
__global__ void ln_kernel(const float* __restrict__ x,
                          const float* __restrict__ w,
                          const float* __restrict__ b,
                          float* __restrict__ y) {
    int row = blockIdx.x;
    const float* xr = x + (size_t)row * DQ;
    float s = 0.f, q = 0.f;
    for (int i = threadIdx.x; i < DQ; i += 256) { float v = xr[i]; s += v; q += v * v; }
    __shared__ float ss[256], sq[256];
    ss[threadIdx.x] = s; sq[threadIdx.x] = q; __syncthreads();
    for (int o = 128; o > 0; o >>= 1) {
        if (threadIdx.x < o) { ss[threadIdx.x] += ss[threadIdx.x + o]; sq[threadIdx.x] += sq[threadIdx.x + o]; }
        __syncthreads();
    }
    float mean = ss[0] * (1.f / DQ);
    float var  = sq[0] * (1.f / DQ) - mean * mean;
    float inv  = rsqrtf(var + 1e-5f);
    float* yr = y + (size_t)row * DQ;
    for (int i = threadIdx.x; i < DQ; i += 256)
        yr[i] = rtf32((xr[i] - mean) * inv * w[i] + b[i]);
}

// ---------------- mma / cp.async / ldmatrix helpers ----------------
__device__ __forceinline__ void mma8(float* c, const uint32_t* a, const uint32_t* b) {
    asm volatile("mma.sync.aligned.m16n8k8.row.col.f32.tf32.tf32.f32 "
                 "{%0,%1,%2,%3}, {%4,%5,%6,%7}, {%8,%9}, {%0,%1,%2,%3};\n"
                 : "+f"(c[0]), "+f"(c[1]), "+f"(c[2]), "+f"(c[3])
                 : "r"(a[0]), "r"(a[1]), "r"(a[2]), "r"(a[3]), "r"(b[0]), "r"(b[1]));
}
__device__ __forceinline__ void cpa16(uint32_t dst, const void* src) {
    asm volatile("cp.async.cg.shared.global [%0], [%1], 16;\n" :: "r"(dst), "l"(src));
}
__device__ __forceinline__ void cpa16z(uint32_t dst, const void* src, int bytes) {
    asm volatile("cp.async.cg.shared.global [%0], [%1], 16, %2;\n" :: "r"(dst), "l"(src), "r"(bytes));
}
__device__ __forceinline__ void ldsm4(uint32_t* r, uint32_t addr) {
    asm volatile("ldmatrix.sync.aligned.m8n8.x4.shared.b16 {%0,%1,%2,%3}, [%4];\n"
                 : "=r"(r[0]), "=r"(r[1]), "=r"(r[2]), "=r"(r[3]) : "r"(addr));
}

// BM=BN=128, BK=32, 2 stages, both tiles [row][k] stride 36.
#define GS 36
#define STG_F (128*GS)                 // floats per tile per stage
#define SMEM_GEMM (4*STG_F*4)          // 2 stages * 2 tiles * 4B = 73728

// ---------------- layer GEMMs: C = A[M,K] * W^T (W is [N][K]) ----------------
template<int EPI>   // 0 bias+round, 1 bias+res, 2 bias+gelu+round
__global__ __launch_bounds__(256, 2)
void gemm_tf32(const float* __restrict__ A, const float* __restrict__ B,
               const float* __restrict__ bias, const float* __restrict__ res,
               float* __restrict__ C, int M, int N, int K) {
    extern __shared__ float sm[];
    float* As = sm;                 // [2][128][36]
    float* Bs = sm + 2 * STG_F;     // [2][128][36]

    const int tid  = threadIdx.x;
    const int lane = tid & 31, wid = tid >> 5;
    const int wm = (wid & 1) * 64, wn = (wid >> 1) * 32;
    const int g = lane >> 2, tq = lane & 3;
    const int m0 = blockIdx.y * 128, n0 = blockIdx.x * 128;

    const uint32_t sAu = (uint32_t)__cvta_generic_to_shared(As);
    const uint32_t sBu = (uint32_t)__cvta_generic_to_shared(Bs);

    const int arow = tid >> 3, acol = (tid & 7) << 2;

    // ldmatrix per-thread row offsets (float units, within a stage)
    const int mrow = lane & 7, msel = lane >> 3;
    const int rsh = (msel & 1) * 8, ksh = (msel & 2) ? 4 : 0;
    int aoff[4], boff[2];
    #pragma unroll
    for (int mi = 0; mi < 4; mi++) aoff[mi] = (wm + mi * 16 + mrow + rsh) * GS + ksh;
    #pragma unroll
    for (int p = 0; p < 2; p++)    boff[p]  = (wn + p * 16 + mrow + rsh) * GS + ksh;

    auto load_tile = [&](int t) {
        int k0 = t * 32, st = t & 1;
        #pragma unroll
        for (int it = 0; it < 4; it++) {
            int r = arow + it * 32;
            cpa16(sAu + ((st * 128 + r) * GS + acol) * 4, A + (size_t)(m0 + r) * K + k0 + acol);
            cpa16(sBu + ((st * 128 + r) * GS + acol) * 4, B + (size_t)(n0 + r) * K + k0 + acol);
        }
    };

    float acc[4][4][4] = {};
    const int nt = K / 32;

    load_tile(0);
    asm volatile("cp.async.commit_group;\n");

    for (int t = 0; t < nt; t++) {
        if (t + 1 < nt) load_tile(t + 1);
        asm volatile("cp.async.commit_group;\n");
        asm volatile("cp.async.wait_group 1;\n");
        __syncthreads();

        const int stA = (t & 1) * STG_F;
        #pragma unroll
        for (int ks = 0; ks < 4; ks++) {
            uint32_t af[4][4], bq[2][4];
            #pragma unroll
            for (int mi = 0; mi < 4; mi++)
                ldsm4(af[mi], sAu + (stA + aoff[mi] + ks * 8) * 4);
            #pragma unroll
            for (int p = 0; p < 2; p++)
                ldsm4(bq[p], sBu + (stA + boff[p] + ks * 8) * 4);
            #pragma unroll
            for (int mi = 0; mi < 4; mi++) {
                #pragma unroll
                for (int ni = 0; ni < 4; ni++) {
                    uint32_t bb[2] = { bq[ni >> 1][ni & 1], bq[ni >> 1][(ni & 1) + 2] };
                    mma8(acc[mi][ni], af[mi], bb);
                }
            }
        }
        __syncthreads();
    }

    #pragma unroll
    for (int mi = 0; mi < 4; mi++) {
        #pragma unroll
        for (int ni = 0; ni < 4; ni++) {
            int m = m0 + wm + mi * 16 + g;
            int n = n0 + wn + ni * 8 + tq * 2;
            #pragma unroll
            for (int half = 0; half < 2; half++) {
                int mm = m + half * 8;
                #pragma unroll
                for (int e = 0; e < 2; e++) {
                    int nn = n + e;
                    float v = acc[mi][ni][half * 2 + e] + bias[nn];
                    if (EPI == 0) v = rtf32(v);
                    if (EPI == 1) v += res[(size_t)mm * N + nn];
                    if (EPI == 2) {
                        v = 0.5f * v * (1.f + erff(v * 0.70710678118654752440f));
                        v = rtf32(v);
                    }
                    C[(size_t)mm * N + nn] = v;
                }
            }
        }
    }
}

// ---------------- LM-head GEMM (tokt [V][K]) + fused NLL partials ----------------
__global__ __launch_bounds__(256, 2)
void gemm_lm(const float* __restrict__ A, const float* __restrict__ B,
             float* __restrict__ C, float* __restrict__ pm, float* __restrict__ ps,
             int M, int N, int K) {
    extern __shared__ float sm[];
    float* As = sm;
    float* Bs = sm + 2 * STG_F;

    const int tid  = threadIdx.x;
    const int lane = tid & 31, wid = tid >> 5;
    const int wm = (wid & 1) * 64, wn = (wid >> 1) * 32;
    const int g = lane >> 2, tq = lane & 3;
    const int m0 = blockIdx.x * 128, n0 = blockIdx.y * 128;
    const int tileY = blockIdx.y, NTt = gridDim.y;

    const uint32_t sAu = (uint32_t)__cvta_generic_to_shared(As);
    const uint32_t sBu = (uint32_t)__cvta_generic_to_shared(Bs);

    const int arow = tid >> 3, acol = (tid & 7) << 2;
    const int mrow = lane & 7, msel = lane >> 3;
    const int rsh = (msel & 1) * 8, ksh = (msel & 2) ? 4 : 0;
    int aoff[4], boff[2];
    #pragma unroll
    for (int mi = 0; mi < 4; mi++) aoff[mi] = (wm + mi * 16 + mrow + rsh) * GS + ksh;
    #pragma unroll
    for (int p = 0; p < 2; p++)    boff[p]  = (wn + p * 16 + mrow + rsh) * GS + ksh;

    auto load_tile = [&](int t) {
        int k0 = t * 32, st = t & 1;
        #pragma unroll
        for (int it = 0; it < 4; it++) {
            int r = arow + it * 32;
            cpa16(sAu + ((st * 128 + r) * GS + acol) * 4, A + (size_t)(m0 + r) * K + k0 + acol);
            int n = n0 + r;
            int ok = (n < N);
            cpa16z(sBu + ((st * 128 + r) * GS + acol) * 4,
                   B + (size_t)(ok ? n : (N - 1)) * K + k0 + acol, ok ? 16 : 0);
        }
    };

    float acc[4][4][4] = {};
    const int nt = K / 32;

    load_tile(0);
    asm volatile("cp.async.commit_group;\n");

    for (int t = 0; t < nt; t++) {
        if (t + 1 < nt) load_tile(t + 1);
        asm volatile("cp.async.commit_group;\n");
        asm volatile("cp.async.wait_group 1;\n");
        __syncthreads();

        const int stA = (t & 1) * STG_F;
        #pragma unroll
        for (int ks = 0; ks < 4; ks++) {
            uint32_t af[4][4], bq[2][4];
            #pragma unroll
            for (int mi = 0; mi < 4; mi++)
                ldsm4(af[mi], sAu + (stA + aoff[mi] + ks * 8) * 4);
            #pragma unroll
            for (int p = 0; p < 2; p++)
                ldsm4(bq[p], sBu + (stA + boff[p] + ks * 8) * 4);
            #pragma unroll
            for (int mi = 0; mi < 4; mi++) {
                #pragma unroll
                for (int ni = 0; ni < 4; ni++) {
                    uint32_t bb[2] = { bq[ni >> 1][ni & 1], bq[ni >> 1][(ni & 1) + 2] };
                    mma8(acc[mi][ni], af[mi], bb);
                }
            }
        }
        __syncthreads();
    }

    // write logits
    #pragma unroll
    for (int mi = 0; mi < 4; mi++) {
        #pragma unroll
        for (int ni = 0; ni < 4; ni++) {
            int m = m0 + wm + mi * 16 + g;
            int n = n0 + wn + ni * 8 + tq * 2;
            #pragma unroll
            for (int half = 0; half < 2; half++) {
                int mm = m + half * 8;
                #pragma unroll
                for (int e = 0; e < 2; e++) {
                    int nn = n + e;
                    if (nn >= N) continue;
                    C[(size_t)mm * N + nn] = acc[mi][ni][half * 2 + e];
                }
            }
        }
    }

    // fused per-tile logsumexp partials
    float* sPm = sm;
    float* sPs = sm + 512;
    __syncthreads();
    #pragma unroll
    for (int mi = 0; mi < 4; mi++) {
        #pragma unroll
        for (int half = 0; half < 2; half++) {
            float lm = -1e30f, lsum = 0.f;
            #pragma unroll
            for (int ni = 0; ni < 4; ni++) {
                #pragma unroll
                for (int e = 0; e < 2; e++) {
                    int nn = n0 + wn + ni * 8 + tq * 2 + e;
                    if (nn < N) lm = fmaxf(lm, acc[mi][ni][half * 2 + e]);
                }
            }
            #pragma unroll
            for (int ni = 0; ni < 4; ni++) {
                #pragma unroll
                for (int e = 0; e < 2; e++) {
                    int nn = n0 + wn + ni * 8 + tq * 2 + e;
                    if (nn < N) lsum += __expf(acc[mi][ni][half * 2 + e] - lm);
                }
            }
            #pragma unroll
            for (int o = 1; o <= 2; o <<= 1) {
                float m2 = __shfl_xor_sync(0xffffffffu, lm, o);
                float s2 = __shfl_xor_sync(0xffffffffu, lsum, o);
                lse_merge(lm, lsum, m2, s2);
            }
            if (tq == 0) {
                int rl = wm + mi * 16 + half * 8 + g;
                sPm[rl * 4 + (wid >> 1)] = lm;
                sPs[rl * 4 + (wid >> 1)] = lsum;
            }
        }
    }
    __syncthreads();
    if (tid < 128) {
        float M_ = sPm[tid * 4], S_ = sPs[tid * 4];
        #pragma unroll
        for (int gi = 1; gi < 4; gi++) lse_merge(M_, S_, sPm[tid * 4 + gi], sPs[tid * 4 + gi]);
        pm[(size_t)(m0 + tid) * NTt + tileY] = M_;
        ps[(size_t)(m0 + tid) * NTt + tileY] = S_;
    }
}

// ---------------- flash attention (tf32 tensor cores) ----------------
#define FQS 68
#define FVS 72
#define SMEM_FL ((64*FQS*2 + 64*FVS)*4)
__global__ __launch_bounds__(128)
void flash_mma(const float* __restrict__ qkv, float* __restrict__ out) {
    extern __shared__ float sm[];
    float* Qs = sm;
    float* Ks = sm + 64 * FQS;
    float* Vs = sm + 2 * 64 * FQS;

    const int tid = threadIdx.x;
    const int lane = tid & 31, wid = tid >> 5;
    const int g = lane >> 2, tq = lane & 3;
    const int q0 = blockIdx.x * 64;
    const int h = blockIdx.y, b = blockIdx.z;
    const int r0 = wid * 16 + g;

    #pragma unroll
    for (int i = 0; i < 8; i++) {
        int idx = tid + i * 128;
        int r = idx >> 4, d0 = (idx & 15) << 2;
        float4 v = *(const float4*)(qkv + (size_t)(b * TQ + q0 + r) * (3 * DQ) + h * HD + d0);
        v.x *= 0.125f; v.y *= 0.125f; v.z *= 0.125f; v.w *= 0.125f;
        *(float4*)(Qs + r * FQS + d0) = v;
    }

    float m0r = -1e30f, m1r = -1e30f, l0 = 0.f, l1 = 0.f;
    float oc[8][4] = {};

    const int ktiles = q0 / 64 + 1;
    for (int kt = 0; kt < ktiles; kt++) {
        int k0 = kt * 64;
        __syncthreads();
        #pragma unroll
        for (int i = 0; i < 8; i++) {
            int idx = tid + i * 128;
            int r = idx >> 4, d0 = (idx & 15) << 2;
            const float* src = qkv + (size_t)(b * TQ + k0 + r) * (3 * DQ) + h * HD + d0;
            *(float4*)(Ks + r * FQS + d0) = *(const float4*)(src + DQ);
            *(float4*)(Vs + r * FVS + d0) = *(const float4*)(src + 2 * DQ);
        }
        __syncthreads();

        float sc[8][4] = {};
        #pragma unroll
        for (int kk = 0; kk < 8; kk++) {
            uint32_t a[4];
            a[0] = __float_as_uint(Qs[r0 * FQS + kk * 8 + tq]);
            a[1] = __float_as_uint(Qs[(r0 + 8) * FQS + kk * 8 + tq]);
            a[2] = __float_as_uint(Qs[r0 * FQS + kk * 8 + tq + 4]);
            a[3] = __float_as_uint(Qs[(r0 + 8) * FQS + kk * 8 + tq + 4]);
            #pragma unroll
            for (int ni = 0; ni < 8; ni++) {
                uint32_t bb[2];
                bb[0] = __float_as_uint(Ks[(ni * 8 + g) * FQS + kk * 8 + tq]);
                bb[1] = __float_as_uint(Ks[(ni * 8 + g) * FQS + kk * 8 + tq + 4]);
                mma8(sc[ni], a, bb);
            }
        }

        if (k0 == q0) {
            #pragma unroll
            for (int ni = 0; ni < 8; ni++) {
                int c0 = ni * 8 + 2 * tq, c1 = c0 + 1;
                if (c0 > r0) sc[ni][0] = -1e30f;
                if (c1 > r0) sc[ni][1] = -1e30f;
                if (c0 > r0 + 8) sc[ni][2] = -1e30f;
                if (c1 > r0 + 8) sc[ni][3] = -1e30f;
            }
        }

        float mx0 = -1e30f, mx1 = -1e30f;
        #pragma unroll
        for (int ni = 0; ni < 8; ni++) {
            mx0 = fmaxf(mx0, fmaxf(sc[ni][0], sc[ni][1]));
            mx1 = fmaxf(mx1, fmaxf(sc[ni][2], sc[ni][3]));
        }
        #pragma unroll
        for (int o = 1; o <= 2; o <<= 1) {
            mx0 = fmaxf(mx0, __shfl_xor_sync(0xffffffffu, mx0, o));
            mx1 = fmaxf(mx1, __shfl_xor_sync(0xffffffffu, mx1, o));
        }
        float nm0 = fmaxf(m0r, mx0), nm1 = fmaxf(m1r, mx1);
        float cr0 = __expf(m0r - nm0), cr1 = __expf(m1r - nm1);
        float rs0 = 0.f, rs1 = 0.f;
        #pragma unroll
        for (int ni = 0; ni < 8; ni++) {
            sc[ni][0] = __expf(sc[ni][0] - nm0); rs0 += sc[ni][0];
            sc[ni][1] = __expf(sc[ni][1] - nm0); rs0 += sc[ni][1];
            sc[ni][2] = __expf(sc[ni][2] - nm1); rs1 += sc[ni][2];
            sc[ni][3] = __expf(sc[ni][3] - nm1); rs1 += sc[ni][3];
        }
        #pragma unroll
        for (int o = 1; o <= 2; o <<= 1) {
            rs0 += __shfl_xor_sync(0xffffffffu, rs0, o);
            rs1 += __shfl_xor_sync(0xffffffffu, rs1, o);
        }
        l0 = l0 * cr0 + rs0; l1 = l1 * cr1 + rs1;
        m0r = nm0; m1r = nm1;
        #pragma unroll
        for (int ni = 0; ni < 8; ni++) {
            oc[ni][0] *= cr0; oc[ni][1] *= cr0;
            oc[ni][2] *= cr1; oc[ni][3] *= cr1;
        }

        __syncthreads();
        #pragma unroll
        for (int ni = 0; ni < 8; ni++) {
            Ks[r0 * FQS + ni * 8 + 2 * tq]           = rtf32(sc[ni][0]);
            Ks[r0 * FQS + ni * 8 + 2 * tq + 1]       = rtf32(sc[ni][1]);
            Ks[(r0 + 8) * FQS + ni * 8 + 2 * tq]     = rtf32(sc[ni][2]);
            Ks[(r0 + 8) * FQS + ni * 8 + 2 * tq + 1] = rtf32(sc[ni][3]);
        }
        __syncthreads();

        #pragma unroll
        for (int kk = 0; kk < 8; kk++) {
            uint32_t a[4];
            a[0] = __float_as_uint(Ks[r0 * FQS + kk * 8 + tq]);
            a[1] = __float_as_uint(Ks[(r0 + 8) * FQS + kk * 8 + tq]);
            a[2] = __float_as_uint(Ks[r0 * FQS + kk * 8 + tq + 4]);
            a[3] = __float_as_uint(Ks[(r0 + 8) * FQS + kk * 8 + tq + 4]);
            #pragma unroll
            for (int ni = 0; ni < 8; ni++) {
                uint32_t bb[2];
                bb[0] = __float_as_uint(Vs[(kk * 8 + tq) * FVS + ni * 8 + g]);
                bb[1] = __float_as_uint(Vs[(kk * 8 + tq + 4) * FVS + ni * 8 + g]);
                mma8(oc[ni], a, bb);
            }
        }
    }

    float i0 = 1.f / l0, i1 = 1.f / l1;
    float* o0 = out + (size_t)(b * TQ + q0 + r0) * DQ + h * HD;
    float* o1 = out + (size_t)(b * TQ + q0 + r0 + 8) * DQ + h * HD;
    #pragma unroll
    for (int ni = 0; ni < 8; ni++) {
        o0[ni * 8 + 2 * tq]     = rtf32(oc[ni][0] * i0);
        o0[ni * 8 + 2 * tq + 1] = rtf32(oc[ni][1] * i0);
        o1[ni * 8 + 2 * tq]     = rtf32(oc[ni][2] * i1);
        o1[ni * 8 + 2 * tq + 1] = rtf32(oc[ni][3] * i1);
    }
}

// ---------------- NLL reduce + loss ----------------
__global__ void nll_reduce(const float* __restrict__ pm, const float* __restrict__ ps,
                           const float* __restrict__ logits, const int* __restrict__ tgt,
                           float* __restrict__ nll) {
    int row = blockIdx.x, t = threadIdx.x;
    float M = -1e30f, S = 0.f;
    for (int j = t; j < NT_LM; j += 128)
        lse_merge(M, S, pm[(size_t)row * NT_LM + j], ps[(size_t)row * NT_LM + j]);
    __shared__ float sm_[128], ss_[128];
    sm_[t] = M; ss_[t] = S; __syncthreads();
    for (int o = 64; o > 0; o >>= 1) {
        if (t < o) {
            float mm = sm_[t], ssv = ss_[t];
            lse_merge(mm, ssv, sm_[t + o], ss_[t + o]);
            sm_[t] = mm; ss_[t] = ssv;
        }
        __syncthreads();
    }
    if (t == 0) {
        float lse = sm_[0] + logf(ss_[0]);
        nll[row] = lse - logits[(size_t)row * VQ + tgt[row]];
    }
}

__global__ void loss_kernel(const float* __restrict__ nll, float* __restrict__ loss) {
    __shared__ float s[1024];
    float v = nll[threadIdx.x] + nll[threadIdx.x + 1024];
    s[threadIdx.x] = v; __syncthreads();
    for (int o = 512; o > 0; o >>= 1) {
        if (threadIdx.x < o) s[threadIdx.x] += s[threadIdx.x + o];
        __syncthreads();
    }
    if (threadIdx.x == 0) *loss = s[0] * (1.f / 2048.f);
}

// ---------------- launch ----------------
extern "C" void kernel_launch(void* const* d_in, const int* in_sizes, int n_in,
                              void* d_out, int out_size) {
    const int*   ids  = (const int*)d_in[0];
    const int*   tgt  = (const int*)d_in[1];
    const float* tok  = (const float*)d_in[2];
    const float* pos  = (const float*)d_in[3];
    const float* ln1w = (const float*)d_in[4];
    const float* ln1b = (const float*)d_in[5];
    const float* qkvw = (const float*)d_in[6];
    const float* qkvb = (const float*)d_in[7];
    const float* apw  = (const float*)d_in[8];
    const float* apb  = (const float*)d_in[9];
    const float* ln2w = (const float*)d_in[10];
    const float* ln2b = (const float*)d_in[11];
    const float* fcw  = (const float*)d_in[12];
    const float* fcb  = (const float*)d_in[13];
    const float* pw   = (const float*)d_in[14];
    const float* pb   = (const float*)d_in[15];
    const float* lnfw = (const float*)d_in[16];
    const float* lnfb = (const float*)d_in[17];

    float *x, *h, *qkv, *attn, *ffn, *nll, *lfb, *pm, *ps;
    float *wqkv, *wap, *wfc, *wpr, *tokt;
    cudaGetSymbolAddress((void**)&x,    g_x);
    cudaGetSymbolAddress((void**)&h,    g_h);
    cudaGetSymbolAddress((void**)&qkv,  g_qkv);
    cudaGetSymbolAddress((void**)&attn, g_attn);
    cudaGetSymbolAddress((void**)&ffn,  g_ffn);
    cudaGetSymbolAddress((void**)&nll,  g_nll);
    cudaGetSymbolAddress((void**)&lfb,  g_logits_fb);
    cudaGetSymbolAddress((void**)&pm,   g_pm);
    cudaGetSymbolAddress((void**)&ps,   g_ps);
    cudaGetSymbolAddress((void**)&wqkv, g_wqkv);
    cudaGetSymbolAddress((void**)&wap,  g_wap);
    cudaGetSymbolAddress((void**)&wfc,  g_wfc);
    cudaGetSymbolAddress((void**)&wpr,  g_wpr);
    cudaGetSymbolAddress((void**)&tokt, g_tokt);

    cudaFuncSetAttribute(flash_mma, cudaFuncAttributeMaxDynamicSharedMemorySize, SMEM_FL);
    cudaFuncSetAttribute(gemm_tf32<0>, cudaFuncAttributeMaxDynamicSharedMemorySize, SMEM_GEMM);
    cudaFuncSetAttribute(gemm_tf32<1>, cudaFuncAttributeMaxDynamicSharedMemorySize, SMEM_GEMM);
    cudaFuncSetAttribute(gemm_tf32<2>, cudaFuncAttributeMaxDynamicSharedMemorySize, SMEM_GEMM);
    cudaFuncSetAttribute(gemm_lm,      cudaFuncAttributeMaxDynamicSharedMemorySize, SMEM_GEMM);

    const long long LOGN = (long long)BT * VQ;
    float* out    = (float*)d_out;
    float* logits;
    float* lossp  = nullptr;
    if ((long long)out_size > LOGN) {
        lossp  = out;
        logits = out + ((long long)out_size - LOGN);
    } else if ((long long)out_size == LOGN) {
        logits = out;
    } else {
        lossp  = out;
        logits = lfb;
    }

    // round + transpose weights to [N][K] tf32; round tok_emb
    cvtT_kernel<<<dim3(DQ/32, 3*DQ/32, LQ), 256>>>(qkvw, wqkv, DQ, 3*DQ);
    cvtT_kernel<<<dim3(DQ/32, DQ/32,   LQ), 256>>>(apw,  wap,  DQ, DQ);
    cvtT_kernel<<<dim3(DQ/32, 4*DQ/32, LQ), 256>>>(fcw,  wfc,  DQ, 4*DQ);
    cvtT_kernel<<<dim3(4*DQ/32, DQ/32, LQ), 256>>>(pw,   wpr,  4*DQ, DQ);
    {
        int n = (int)((size_t)VQ*DQ/4);
        cvt_kernel<<<(n+255)/256, 256>>>((const float4*)tok, (float4*)tokt, n);
    }

    embed_kernel<<<(BT * DQ + 255) / 256, 256>>>(ids, tok, pos, x);

    for (int l = 0; l < LQ; l++) {
        ln_kernel<<<BT, 256>>>(x, ln1w + l * DQ, ln1b + l * DQ, h);
        gemm_tf32<0><<<dim3((3 * DQ) / 128, BT / 128), 256, SMEM_GEMM>>>(
            h, wqkv + (size_t)l * DQ * 3 * DQ, qkvb + l * 3 * DQ, nullptr, qkv, BT, 3 * DQ, DQ);
        flash_mma<<<dim3(TQ / 64, HQ, BQ), 128, SMEM_FL>>>(qkv, attn);
        gemm_tf32<1><<<dim3(DQ / 128, BT / 128), 256, SMEM_GEMM>>>(
            attn, wap + (size_t)l * DQ * DQ, apb + l * DQ, x, x, BT, DQ, DQ);
        ln_kernel<<<BT, 256>>>(x, ln2w + l * DQ, ln2b + l * DQ, h);
        gemm_tf32<2><<<dim3((4 * DQ) / 128, BT / 128), 256, SMEM_GEMM>>>(
            h, wfc + (size_t)l * DQ * 4 * DQ, fcb + l * 4 * DQ, nullptr, ffn, BT, 4 * DQ, DQ);
        gemm_tf32<1><<<dim3(DQ / 128, BT / 128), 256, SMEM_GEMM>>>(
            ffn, wpr + (size_t)l * 4 * DQ * DQ, pb + l * DQ, x, x, BT, DQ, 4 * DQ);
    }

    ln_kernel<<<BT, 256>>>(x, lnfw, lnfb, h);
    gemm_lm<<<dim3(BT / 128, NT_LM), 256, SMEM_GEMM>>>(
        h, tokt, logits, pm, ps, BT, VQ, DQ);

    if (lossp) {
        nll_reduce<<<BT, 128>>>(pm, ps, logits, tgt, nll);
        loss_kernel<<<1, 1024>>>(nll, lossp);
    }
}